// round 10
// baseline (speedup 1.0000x reference)
#include <cuda_runtime.h>
#include <cuda_bf16.h>
#include <cuda_fp16.h>
#include <cstdint>
#include <math.h>

// ---------------- problem constants ----------------
#define T_TOK   8192
#define DIM     2048
#define NH      16
#define NKV     8
#define HD      128
#define S_LEN   1024
#define B_SZ    8
#define KV_DIM  1024      // NKV * HD
#define QKV_N   4096      // DIM + 2*KV_DIM

// ---------------- scratch ----------------
__device__ float g_qkv[T_TOK * QKV_N];     // fused QKV GEMM output

// fp16 hi/lo splits for GEMM activations
__device__ __half g_xh[T_TOK * DIM];
__device__ __half g_xl[T_TOK * DIM];
__device__ __half g_ah[T_TOK * DIM];       // attn out split hi
__device__ __half g_al[T_TOK * DIM];       // attn out split lo
// fp16 transposed weights [N,K]
__device__ __half g_wqkvT[QKV_N * DIM];    // rows: 0-2047 wq^T, 2048-3071 wk^T, 3072-4095 wv^T
__device__ __half g_woT[DIM * DIM];
// fp16 attention operands
__device__ __half g_qbh[T_TOK * DIM];      // q hi (exact split with g_qbl)
__device__ __half g_qbl[T_TOK * DIM];
__device__ __half g_kf[T_TOK * KV_DIM];    // k single fp16 (rounded)
__device__ __half g_vf[T_TOK * KV_DIM];    // v single fp16 (rounded)

// ================= low-level helpers (sm_80-class PTX only) =================
__device__ __forceinline__ uint32_t smem_to_u32(const void* smem_ptr) {
    uint32_t addr;
    asm("{ .reg .u64 tmp; cvta.to.shared.u64 tmp, %1; cvt.u32.u64 %0, tmp; }"
        : "=r"(addr) : "l"(smem_ptr));
    return addr;
}

#define CP_ASYNC16(dst_u32, src_ptr) \
    asm volatile("cp.async.cg.shared.global [%0], [%1], 16;" \
                 :: "r"(dst_u32), "l"(src_ptr) : "memory")
#define CP_COMMIT() asm volatile("cp.async.commit_group;" ::: "memory")
#define CP_WAIT0()  asm volatile("cp.async.wait_group 0;" ::: "memory")
#define CP_WAIT1()  asm volatile("cp.async.wait_group 1;" ::: "memory")

__device__ __forceinline__ void ldm_x4(uint32_t* r, uint32_t addr) {
    asm volatile("ldmatrix.sync.aligned.m8n8.x4.shared.b16 {%0,%1,%2,%3}, [%4];"
                 : "=r"(r[0]), "=r"(r[1]), "=r"(r[2]), "=r"(r[3]) : "r"(addr));
}
__device__ __forceinline__ void ldm_x2(uint32_t* r, uint32_t addr) {
    asm volatile("ldmatrix.sync.aligned.m8n8.x2.shared.b16 {%0,%1}, [%2];"
                 : "=r"(r[0]), "=r"(r[1]) : "r"(addr));
}
__device__ __forceinline__ void ldm_x2_trans(uint32_t* r, uint32_t addr) {
    asm volatile("ldmatrix.sync.aligned.m8n8.x2.trans.shared.b16 {%0,%1}, [%2];"
                 : "=r"(r[0]), "=r"(r[1]) : "r"(addr));
}
// fp16 mma
__device__ __forceinline__ void mma16816h(float* c, const uint32_t* a, const uint32_t* b) {
    asm volatile("mma.sync.aligned.m16n8k16.row.col.f32.f16.f16.f32 "
                 "{%0,%1,%2,%3}, {%4,%5,%6,%7}, {%8,%9}, {%0,%1,%2,%3};"
                 : "+f"(c[0]), "+f"(c[1]), "+f"(c[2]), "+f"(c[3])
                 : "r"(a[0]), "r"(a[1]), "r"(a[2]), "r"(a[3]), "r"(b[0]), "r"(b[1]));
}
// pack two fp32 into f16x2 word: mem-low half = first arg
__device__ __forceinline__ uint32_t packh(float lo, float hi) {
    __half2 h = __floats2half2_rn(lo, hi);
    return *(uint32_t*)&h;
}

// ================= fp16 2-pass mma.sync GEMM =================
// C[M,N] = A[M,K] @ W[K,N];  A as (Ah+Al) fp16 [M,K] K-major, W^T as Bh fp16 [N,K].
// CTA tile 128x128, K-tile 32, 3-stage cp.async pipeline.
#define GT_ROWB   80
#define GT_TILE   (128 * GT_ROWB)          // 10240 B
#define GT_STAGE  (3 * GT_TILE)            // Ah, Al, Bh = 30720 B
#define GT_NST    3
#define GT_TOTAL  (GT_NST * GT_STAGE)      // 92160 B -> 2 CTAs/SM

__global__ __launch_bounds__(256, 2)
void gemm_h2(const __half* __restrict__ Ah, const __half* __restrict__ Al,
             const __half* __restrict__ Bh, float* __restrict__ C, int Ncols, int K)
{
    extern __shared__ char smc[];
    const uint32_t sbase = smem_to_u32(smc);

    const int tid  = threadIdx.x;
    const int lane = tid & 31;
    const int wid  = tid >> 5;
    const int bx = blockIdx.x;
    const int by = blockIdx.y;
    const int m0 = (wid & 1) * 64;
    const int n0 = (wid >> 1) * 32;

    const int r0c = tid >> 2,          c0c = tid & 3;
    const int r1c = (tid + 256) >> 2,  c1c = tid & 3;

    const size_t ga0 = (size_t)(by * 128 + r0c) * K + c0c * 8;
    const size_t ga1 = (size_t)(by * 128 + r1c) * K + c1c * 8;
    const size_t gb0 = (size_t)(bx * 128 + r0c) * K + c0c * 8;
    const size_t gb1 = (size_t)(bx * 128 + r1c) * K + c1c * 8;
    const uint32_t so0 = r0c * GT_ROWB + c0c * 16;
    const uint32_t so1 = r1c * GT_ROWB + c1c * 16;

    float acc[4][4][4];
#pragma unroll
    for (int i = 0; i < 4; i++)
#pragma unroll
        for (int j = 0; j < 4; j++)
#pragma unroll
            for (int e = 0; e < 4; e++) acc[i][j][e] = 0.f;

    const int n_kt = K >> 5;

    const uint32_t a_row = (uint32_t)(m0 + (lane & 15));
    const uint32_t a_coloff = (uint32_t)((lane >> 4) * 16);
    const uint32_t b_row = (uint32_t)(n0 + (lane & 7));
    const uint32_t b_coloff = (uint32_t)(((lane >> 3) & 1) * 16);

#define GLOAD_STAGE(sidx, ko)                                              \
    do {                                                                   \
        const uint32_t st_ = sbase + (sidx) * GT_STAGE;                    \
        CP_ASYNC16(st_ + 0 * GT_TILE + so0, Ah + ga0 + (ko));              \
        CP_ASYNC16(st_ + 0 * GT_TILE + so1, Ah + ga1 + (ko));              \
        CP_ASYNC16(st_ + 1 * GT_TILE + so0, Al + ga0 + (ko));              \
        CP_ASYNC16(st_ + 1 * GT_TILE + so1, Al + ga1 + (ko));              \
        CP_ASYNC16(st_ + 2 * GT_TILE + so0, Bh + gb0 + (ko));              \
        CP_ASYNC16(st_ + 2 * GT_TILE + so1, Bh + gb1 + (ko));              \
        CP_COMMIT();                                                       \
    } while (0)

    GLOAD_STAGE(0, 0);
    GLOAD_STAGE(1, 32);

    int sidx = 0;
    for (int kt = 0; kt < n_kt; kt++) {
        if (kt + 1 < n_kt) { CP_WAIT1(); } else { CP_WAIT0(); }
        __syncthreads();
        if (kt + 2 < n_kt) {
            int sn = sidx + 2; if (sn >= GT_NST) sn -= GT_NST;
            GLOAD_STAGE(sn, (size_t)(kt + 2) * 32);
        }

        const uint32_t st = sbase + sidx * GT_STAGE;
        const uint32_t sAh = st;
        const uint32_t sAl = st + 1 * GT_TILE;
        const uint32_t sBh = st + 2 * GT_TILE;

#pragma unroll
        for (int ks = 0; ks < 2; ks++) {
            const uint32_t kb = ks * 32;
            uint32_t af[4][4], bf[4][2];
#pragma unroll
            for (int mt = 0; mt < 4; mt++)
                ldm_x4(af[mt], sAh + (a_row + mt * 16) * GT_ROWB + kb + a_coloff);
#pragma unroll
            for (int nt = 0; nt < 4; nt++)
                ldm_x2(bf[nt], sBh + (b_row + nt * 8) * GT_ROWB + kb + b_coloff);
#pragma unroll
            for (int mt = 0; mt < 4; mt++)
#pragma unroll
                for (int nt = 0; nt < 4; nt++)
                    mma16816h(acc[mt][nt], af[mt], bf[nt]);
#pragma unroll
            for (int mt = 0; mt < 4; mt++)
                ldm_x4(af[mt], sAl + (a_row + mt * 16) * GT_ROWB + kb + a_coloff);
#pragma unroll
            for (int mt = 0; mt < 4; mt++)
#pragma unroll
                for (int nt = 0; nt < 4; nt++)
                    mma16816h(acc[mt][nt], af[mt], bf[nt]);
        }
        sidx++; if (sidx >= GT_NST) sidx -= GT_NST;
    }

    const int g  = lane >> 2;
    const int tg = (lane & 3) * 2;
#pragma unroll
    for (int mt = 0; mt < 4; mt++) {
        const int r = by * 128 + m0 + mt * 16 + g;
#pragma unroll
        for (int nt = 0; nt < 4; nt++) {
            const int cc = bx * 128 + n0 + nt * 8 + tg;
            *(float2*)(C + (size_t)r * Ncols + cc) =
                make_float2(acc[mt][nt][0], acc[mt][nt][1]);
            *(float2*)(C + (size_t)(r + 8) * Ncols + cc) =
                make_float2(acc[mt][nt][2], acc[mt][nt][3]);
        }
    }
}

// ---------------- fp32 -> fp16 hi/lo split ----------------
__global__ __launch_bounds__(256)
void convert_split_h(const float* __restrict__ X, __half* __restrict__ H,
                     __half* __restrict__ L, int total)
{
    int i = blockIdx.x * blockDim.x + threadIdx.x;
    if (i >= total) return;
    float v = X[i];
    __half h = __float2half_rn(v);
    H[i] = h;
    L[i] = __float2half_rn(v - __half2float(h));
}

// ---------------- strided fp32 -> fp16 (V path from fused QKV buffer) ----------------
__global__ __launch_bounds__(256)
void convert_v_h(const float* __restrict__ QKV, __half* __restrict__ V, int total)
{
    int i = blockIdx.x * blockDim.x + threadIdx.x;
    if (i >= total) return;
    int t = i >> 10;            // / KV_DIM
    int c = i & 1023;
    V[i] = __float2half_rn(QKV[(size_t)t * QKV_N + 3072 + c]);
}

// ---------------- W[K,N] -> W^T fp16 [N,K] ----------------
__global__ __launch_bounds__(256)
void transpose_h(const float* __restrict__ W, __half* __restrict__ Th, int K, int N)
{
    __shared__ float t[32][33];
    int n0 = blockIdx.x * 32, k0 = blockIdx.y * 32;
    int tx = threadIdx.x & 31, ty = threadIdx.x >> 5;
#pragma unroll
    for (int j = 0; j < 4; j++)
        t[ty + j * 8][tx] = W[(size_t)(k0 + ty + j * 8) * N + n0 + tx];
    __syncthreads();
#pragma unroll
    for (int j = 0; j < 4; j++)
        Th[(size_t)(n0 + ty + j * 8) * K + k0 + tx] = __float2half_rn(t[tx][ty + j * 8]);
}

// ---------------- RoPE variants (read strided fused QKV buffer) ----------------
// q: rotate + scale, write exact fp16 hi/lo
__global__ __launch_bounds__(256)
void rope_q_split(const float* __restrict__ QKV, const int* __restrict__ positions,
                  __half* __restrict__ H, __half* __restrict__ L)
{
    int idx = blockIdx.x * blockDim.x + threadIdx.x;
    if (idx >= T_TOK * NH * 64) return;
    int pair = idx & 63;
    int h    = (idx >> 6) & 15;
    int t    = idx >> 10;
    double inv = pow(10000.0, -(double)(2 * pair) / 128.0);
    double ang = (double)positions[t] * inv;
    float c = (float)cos(ang);
    float s = (float)sin(ang);
    const float scale = 0.08838834764831845f;
    size_t o_s = (size_t)t * QKV_N + h * HD + 2 * pair;
    size_t o_d = (size_t)t * DIM + h * HD + 2 * pair;
    float xr = QKV[o_s], xi = QKV[o_s + 1];
    float vr = (xr * c - xi * s) * scale;
    float vi = (xr * s + xi * c) * scale;
    __half hr = __float2half_rn(vr);
    __half hh = __float2half_rn(vi);
    H[o_d]     = hr;
    H[o_d + 1] = hh;
    L[o_d]     = __float2half_rn(vr - __half2float(hr));
    L[o_d + 1] = __float2half_rn(vi - __half2float(hh));
}

// k: rotate, write single fp16
__global__ __launch_bounds__(256)
void rope_k_h(const float* __restrict__ QKV, const int* __restrict__ positions,
              __half* __restrict__ Kf)
{
    int idx = blockIdx.x * blockDim.x + threadIdx.x;
    if (idx >= T_TOK * NKV * 64) return;
    int pair = idx & 63;
    int h    = (idx >> 6) & 7;
    int t    = idx >> 9;
    double inv = pow(10000.0, -(double)(2 * pair) / 128.0);
    double ang = (double)positions[t] * inv;
    float c = (float)cos(ang);
    float s = (float)sin(ang);
    size_t o_s = (size_t)t * QKV_N + 2048 + h * HD + 2 * pair;
    size_t o_d = (size_t)t * KV_DIM + h * HD + 2 * pair;
    float xr = QKV[o_s], xi = QKV[o_s + 1];
    Kf[o_d]     = __float2half_rn(xr * c - xi * s);
    Kf[o_d + 1] = __float2half_rn(xr * s + xi * c);
}

// ================= mma.sync flash attention (causal, GQA rep=2), fp16 2-pass =================
// BQ=128, BK=64. grid (S/128, NH, B), 256 threads (8 warps).
// smem: Qh,Ql [128][128]h + double-buffered K,V [64][128]h; row stride 272 B.
#define AQ_ROWB 272
#define AQ_TILE (128 * AQ_ROWB)        // 34816
#define AKV_TILE (64 * AQ_ROWB)        // 17408
#define AKV_BUF (2 * AKV_TILE)         // 34816 (K + V)
#define AT_SMEM (2 * AQ_TILE + 2 * AKV_BUF)   // 139264 B -> 1 CTA/SM

__global__ __launch_bounds__(256, 1)
void attn_mma(const __half* __restrict__ qh, const __half* __restrict__ ql,
              const __half* __restrict__ kf, const __half* __restrict__ vf,
              __half* __restrict__ oh, __half* __restrict__ ol)
{
    extern __shared__ char smb[];
    const uint32_t sb  = smem_to_u32(smb);
    const uint32_t sQh = sb;
    const uint32_t sQl = sb + AQ_TILE;
    const uint32_t kv0 = sb + 2 * AQ_TILE;

    const int tid  = threadIdx.x;
    const int lane = tid & 31;
    const int wid  = tid >> 5;
    const int qt = blockIdx.x, h = blockIdx.y, b = blockIdx.z;
    const int kvh = h >> 1;
    const int q0 = qt * 128;
    const int m0 = wid * 16;
    const int g  = lane >> 2;
    const int tg = lane & 3;

    // --- Q tiles (hi+lo), 128 rows, loaded once ---
    {
        const __half* srcH = qh + (size_t)(b * S_LEN + q0) * DIM + h * HD;
        const __half* srcL = ql + (size_t)(b * S_LEN + q0) * DIM + h * HD;
        for (int c = tid; c < 2048; c += 256) {
            int r = c >> 4, cc = c & 15;
            CP_ASYNC16(sQh + r * AQ_ROWB + cc * 16, srcH + (size_t)r * DIM + cc * 8);
            CP_ASYNC16(sQl + r * AQ_ROWB + cc * 16, srcL + (size_t)r * DIM + cc * 8);
        }
        CP_COMMIT();
    }

    const size_t kvbase0 = (size_t)(b * S_LEN) * KV_DIM + kvh * HD;

    // prologue: KV tile 0 -> buffer 0
    {
        const __half* pK = kf + kvbase0;
        const __half* pV = vf + kvbase0;
        for (int c = tid; c < 1024; c += 256) {
            int r = c >> 4, cc = c & 15;
            uint32_t so = r * AQ_ROWB + cc * 16;
            size_t go = (size_t)r * KV_DIM + cc * 8;
            CP_ASYNC16(kv0 + 0 * AKV_TILE + so, pK + go);
            CP_ASYNC16(kv0 + 1 * AKV_TILE + so, pV + go);
        }
        CP_COMMIT();
    }

    float oacc[16][4];
#pragma unroll
    for (int nt = 0; nt < 16; nt++)
#pragma unroll
        for (int e = 0; e < 4; e++) oacc[nt][e] = 0.f;
    float mst0 = -1e30f, mst1 = -1e30f, lst0 = 0.f, lst1 = 0.f;

    const uint32_t qa_off = (uint32_t)((m0 + (lane & 15)) * AQ_ROWB + (lane >> 4) * 16);
    const uint32_t kb_row = (uint32_t)((lane & 7) * AQ_ROWB + ((lane >> 3) & 1) * 16);
    const uint32_t v_row  = (uint32_t)((lane & 15) * AQ_ROWB);

    const int ktmax = 2 * qt + 1;
    for (int kt = 0; kt <= ktmax; kt++) {
        const int cur = kt & 1;
        CP_WAIT0();
        __syncthreads();

        // prefetch next KV tile into the other buffer
        if (kt < ktmax) {
            const uint32_t kvn = kv0 + (cur ^ 1) * AKV_BUF;
            const size_t base = kvbase0 + (size_t)(kt + 1) * 64 * KV_DIM;
            const __half* pK = kf + base;
            const __half* pV = vf + base;
            for (int c = tid; c < 1024; c += 256) {
                int r = c >> 4, cc = c & 15;
                uint32_t so = r * AQ_ROWB + cc * 16;
                size_t go = (size_t)r * KV_DIM + cc * 8;
                CP_ASYNC16(kvn + 0 * AKV_TILE + so, pK + go);
                CP_ASYNC16(kvn + 1 * AKV_TILE + so, pV + go);
            }
            CP_COMMIT();
        }

        const uint32_t sK = kv0 + cur * AKV_BUF;
        const uint32_t sV = sK + AKV_TILE;

        // --- S = Q.K^T, fp16 2-pass (Q exact hi+lo, K rounded) ---
        float sacc[8][4];
#pragma unroll
        for (int j = 0; j < 8; j++)
#pragma unroll
            for (int e = 0; e < 4; e++) sacc[j][e] = 0.f;

#pragma unroll
        for (int kk = 0; kk < 8; kk++) {
            uint32_t qfh[4], qfl[4], kfr[2];
            ldm_x4(qfh, sQh + qa_off + kk * 32);
            ldm_x4(qfl, sQl + qa_off + kk * 32);
#pragma unroll
            for (int j = 0; j < 8; j++) {
                ldm_x2(kfr, sK + j * 8 * AQ_ROWB + kb_row + kk * 32);
                mma16816h(sacc[j], qfh, kfr);
                mma16816h(sacc[j], qfl, kfr);
            }
        }

        // --- causal mask ---
        if (kt * 64 + 63 > q0 + m0 + g) {
            const int r0l = q0 + m0 + g, r1l = r0l + 8;
            const int cb = kt * 64 + tg * 2;
#pragma unroll
            for (int j = 0; j < 8; j++) {
                const int c0 = cb + j * 8;
                if (c0     > r0l) sacc[j][0] = -1e30f;
                if (c0 + 1 > r0l) sacc[j][1] = -1e30f;
                if (c0     > r1l) sacc[j][2] = -1e30f;
                if (c0 + 1 > r1l) sacc[j][3] = -1e30f;
            }
        }

        // --- online softmax ---
        float mx0 = -1e30f, mx1 = -1e30f;
#pragma unroll
        for (int j = 0; j < 8; j++) {
            mx0 = fmaxf(mx0, fmaxf(sacc[j][0], sacc[j][1]));
            mx1 = fmaxf(mx1, fmaxf(sacc[j][2], sacc[j][3]));
        }
        mx0 = fmaxf(mx0, __shfl_xor_sync(0xffffffffu, mx0, 1));
        mx0 = fmaxf(mx0, __shfl_xor_sync(0xffffffffu, mx0, 2));
        mx1 = fmaxf(mx1, __shfl_xor_sync(0xffffffffu, mx1, 1));
        mx1 = fmaxf(mx1, __shfl_xor_sync(0xffffffffu, mx1, 2));
        const float nm0 = fmaxf(mst0, mx0);
        const float nm1 = fmaxf(mst1, mx1);
        const float a0 = expf(mst0 - nm0);
        const float a1 = expf(mst1 - nm1);
        mst0 = nm0; mst1 = nm1;
        float sum0 = 0.f, sum1 = 0.f;
#pragma unroll
        for (int j = 0; j < 8; j++) {
            sacc[j][0] = expf(sacc[j][0] - nm0);
            sacc[j][1] = expf(sacc[j][1] - nm0);
            sacc[j][2] = expf(sacc[j][2] - nm1);
            sacc[j][3] = expf(sacc[j][3] - nm1);
            sum0 += sacc[j][0] + sacc[j][1];
            sum1 += sacc[j][2] + sacc[j][3];
        }
        sum0 += __shfl_xor_sync(0xffffffffu, sum0, 1);
        sum0 += __shfl_xor_sync(0xffffffffu, sum0, 2);
        sum1 += __shfl_xor_sync(0xffffffffu, sum1, 1);
        sum1 += __shfl_xor_sync(0xffffffffu, sum1, 2);
        lst0 = lst0 * a0 + sum0;
        lst1 = lst1 * a1 + sum1;
#pragma unroll
        for (int nt = 0; nt < 16; nt++) {
            oacc[nt][0] *= a0; oacc[nt][1] *= a0;
            oacc[nt][2] *= a1; oacc[nt][3] *= a1;
        }

        // --- O += P.V, fp16 2-pass (P exact hi+lo, V rounded) ---
#pragma unroll
        for (int jk = 0; jk < 4; jk++) {
            uint32_t pfh[4], pfl[4];
#pragma unroll
            for (int q = 0; q < 2; q++) {
                const int j = 2 * jk + q;
#pragma unroll
                for (int pr = 0; pr < 2; pr++) {
                    float p0 = sacc[j][2 * pr], p1 = sacc[j][2 * pr + 1];
                    __half b0 = __float2half_rn(p0);
                    __half b1 = __float2half_rn(p1);
                    { __half2 t2 = __halves2half2(b0, b1); pfh[2 * q + pr] = *(uint32_t*)&t2; }
                    pfl[2 * q + pr] = packh(p0 - __half2float(b0),
                                            p1 - __half2float(b1));
                }
            }
            const uint32_t vbase = jk * 16 * AQ_ROWB + v_row;
#pragma unroll
            for (int nt = 0; nt < 16; nt++) {
                uint32_t vfr[2];
                ldm_x2_trans(vfr, sV + vbase + nt * 16);
                mma16816h(oacc[nt], pfh, vfr);
                mma16816h(oacc[nt], pfl, vfr);
            }
        }
    }

    // --- epilogue: normalize, fp16 hi/lo split, store ---
    const float inv0 = 1.f / lst0;
    const float inv1 = 1.f / lst1;
    const size_t r0g = (size_t)(b * S_LEN + q0 + m0 + g);
    const size_t r1g = r0g + 8;
    const int colb = h * HD + tg * 2;
#pragma unroll
    for (int nt = 0; nt < 16; nt++) {
        float v00 = oacc[nt][0] * inv0, v01 = oacc[nt][1] * inv0;
        float v10 = oacc[nt][2] * inv1, v11 = oacc[nt][3] * inv1;
        __half h00 = __float2half_rn(v00), h01 = __float2half_rn(v01);
        __half h10 = __float2half_rn(v10), h11 = __float2half_rn(v11);
        uint32_t hw0, hw1;
        { __half2 t2 = __halves2half2(h00, h01); hw0 = *(uint32_t*)&t2; }
        { __half2 t2 = __halves2half2(h10, h11); hw1 = *(uint32_t*)&t2; }
        uint32_t lw0 = packh(v00 - __half2float(h00), v01 - __half2float(h01));
        uint32_t lw1 = packh(v10 - __half2float(h10), v11 - __half2float(h11));
        const int cc = colb + nt * 8;
        *(uint32_t*)(oh + r0g * DIM + cc) = hw0;
        *(uint32_t*)(ol + r0g * DIM + cc) = lw0;
        *(uint32_t*)(oh + r1g * DIM + cc) = hw1;
        *(uint32_t*)(ol + r1g * DIM + cc) = lw1;
    }
}

// ---------------- launcher ----------------
extern "C" void kernel_launch(void* const* d_in, const int* in_sizes, int n_in,
                              void* d_out, int out_size)
{
    const float* x  = (const float*)d_in[0];
    const float* wq = (const float*)d_in[1];
    const float* wk = (const float*)d_in[2];
    const float* wv = (const float*)d_in[3];
    const float* wo = (const float*)d_in[4];
    const int* positions = (const int*)d_in[7];
    float* out = (float*)d_out;

    float* pqkv;
    cudaGetSymbolAddress((void**)&pqkv, g_qkv);

    __half *xh, *xl, *ah, *al, *wqkvT, *woT, *qbh, *qbl, *pkf, *pvf;
    cudaGetSymbolAddress((void**)&xh, g_xh);
    cudaGetSymbolAddress((void**)&xl, g_xl);
    cudaGetSymbolAddress((void**)&ah, g_ah);
    cudaGetSymbolAddress((void**)&al, g_al);
    cudaGetSymbolAddress((void**)&wqkvT, g_wqkvT);
    cudaGetSymbolAddress((void**)&woT, g_woT);
    cudaGetSymbolAddress((void**)&qbh, g_qbh);
    cudaGetSymbolAddress((void**)&qbl, g_qbl);
    cudaGetSymbolAddress((void**)&pkf, g_kf);
    cudaGetSymbolAddress((void**)&pvf, g_vf);

    cudaFuncSetAttribute(gemm_h2,  cudaFuncAttributeMaxDynamicSharedMemorySize, GT_TOTAL);
    cudaFuncSetAttribute(attn_mma, cudaFuncAttributeMaxDynamicSharedMemorySize, AT_SMEM);

    // 1: x -> fp16 hi/lo
    {
        int total = T_TOK * DIM;
        convert_split_h<<<(total + 255) / 256, 256>>>(x, xh, xl, total);
    }
    // 2-4: weight transposes into concatenated wqkv^T
    transpose_h<<<dim3(DIM / 32,    DIM / 32), 256>>>(wq, wqkvT,                    DIM, DIM);
    transpose_h<<<dim3(KV_DIM / 32, DIM / 32), 256>>>(wk, wqkvT + 2048 * DIM,       DIM, KV_DIM);
    transpose_h<<<dim3(KV_DIM / 32, DIM / 32), 256>>>(wv, wqkvT + 3072 * DIM,       DIM, KV_DIM);
    // 5: fused QKV GEMM  (ncu -s 5 -c 1 should land here given ~1 harness launch)
    gemm_h2<<<dim3(QKV_N / 128, T_TOK / 128), 256, GT_TOTAL>>>(xh, xl, wqkvT, pqkv, QKV_N, DIM);
    // 6: wo transpose
    transpose_h<<<dim3(DIM / 32, DIM / 32), 256>>>(wo, woT, DIM, DIM);
    // 7-9: RoPE + converts
    {
        int total_q = T_TOK * NH * 64;
        int total_k = T_TOK * NKV * 64;
        rope_q_split<<<(total_q + 255) / 256, 256>>>(pqkv, positions, qbh, qbl);
        rope_k_h<<<(total_k + 255) / 256, 256>>>(pqkv, positions, pkf);
        int total_v = T_TOK * KV_DIM;
        convert_v_h<<<(total_v + 255) / 256, 256>>>(pqkv, pvf, total_v);
    }
    // 10: flash attention
    attn_mma<<<dim3(S_LEN / 128, NH, B_SZ), 256, AT_SMEM>>>(qbh, qbl, pkf, pvf, ah, al);
    // 11: output projection
    gemm_h2<<<dim3(DIM / 128, T_TOK / 128), 256, GT_TOTAL>>>(ah, al, woT, out, DIM, DIM);
}

// round 11
// speedup vs baseline: 3.6353x; 3.6353x over previous
#include <cuda_runtime.h>
#include <cuda_bf16.h>
#include <cuda_fp16.h>
#include <cstdint>
#include <math.h>

// ---------------- problem constants ----------------
#define T_TOK   8192
#define DIM     2048
#define NH      16
#define NKV     8
#define HD      128
#define S_LEN   1024
#define B_SZ    8
#define KV_DIM  1024      // NKV * HD
#define QKV_N   4096      // DIM + 2*KV_DIM

// ---------------- scratch ----------------
__device__ float g_qkv[T_TOK * QKV_N];     // fused QKV GEMM output

__device__ float2 g_rope[S_LEN * 64];      // cos/sin per (pos, pair)

// fp16 activations
__device__ __half g_xf[T_TOK * DIM];       // x single fp16 (QKV gemm A)
__device__ __half g_ah[T_TOK * DIM];       // attn out split hi (exact, for wo gemm)
__device__ __half g_al[T_TOK * DIM];       // attn out split lo
// fp16 transposed weights [N,K]
__device__ __half g_wqkvT[QKV_N * DIM];    // rows: 0-2047 wq^T, 2048-3071 wk^T, 3072-4095 wv^T
__device__ __half g_woT[DIM * DIM];
// fp16 attention operands
__device__ __half g_qbh[T_TOK * DIM];      // q hi (exact split with g_qbl)
__device__ __half g_qbl[T_TOK * DIM];
__device__ __half g_kf[T_TOK * KV_DIM];    // k single fp16
__device__ __half g_vf[T_TOK * KV_DIM];    // v single fp16

// ================= low-level helpers (sm_80-class PTX only) =================
__device__ __forceinline__ uint32_t smem_to_u32(const void* smem_ptr) {
    uint32_t addr;
    asm("{ .reg .u64 tmp; cvta.to.shared.u64 tmp, %1; cvt.u32.u64 %0, tmp; }"
        : "=r"(addr) : "l"(smem_ptr));
    return addr;
}

#define CP_ASYNC16(dst_u32, src_ptr) \
    asm volatile("cp.async.cg.shared.global [%0], [%1], 16;" \
                 :: "r"(dst_u32), "l"(src_ptr) : "memory")
#define CP_COMMIT() asm volatile("cp.async.commit_group;" ::: "memory")
#define CP_WAIT0()  asm volatile("cp.async.wait_group 0;" ::: "memory")
#define CP_WAIT1()  asm volatile("cp.async.wait_group 1;" ::: "memory")

__device__ __forceinline__ void ldm_x4(uint32_t* r, uint32_t addr) {
    asm volatile("ldmatrix.sync.aligned.m8n8.x4.shared.b16 {%0,%1,%2,%3}, [%4];"
                 : "=r"(r[0]), "=r"(r[1]), "=r"(r[2]), "=r"(r[3]) : "r"(addr));
}
__device__ __forceinline__ void ldm_x2(uint32_t* r, uint32_t addr) {
    asm volatile("ldmatrix.sync.aligned.m8n8.x2.shared.b16 {%0,%1}, [%2];"
                 : "=r"(r[0]), "=r"(r[1]) : "r"(addr));
}
__device__ __forceinline__ void ldm_x2_trans(uint32_t* r, uint32_t addr) {
    asm volatile("ldmatrix.sync.aligned.m8n8.x2.trans.shared.b16 {%0,%1}, [%2];"
                 : "=r"(r[0]), "=r"(r[1]) : "r"(addr));
}
// fp16 mma
__device__ __forceinline__ void mma16816h(float* c, const uint32_t* a, const uint32_t* b) {
    asm volatile("mma.sync.aligned.m16n8k16.row.col.f32.f16.f16.f32 "
                 "{%0,%1,%2,%3}, {%4,%5,%6,%7}, {%8,%9}, {%0,%1,%2,%3};"
                 : "+f"(c[0]), "+f"(c[1]), "+f"(c[2]), "+f"(c[3])
                 : "r"(a[0]), "r"(a[1]), "r"(a[2]), "r"(a[3]), "r"(b[0]), "r"(b[1]));
}
__device__ __forceinline__ uint32_t packh(float lo, float hi) {
    __half2 h = __floats2half2_rn(lo, hi);
    return *(uint32_t*)&h;
}

// ================= fp16 single-pass GEMM (QKV) =================
// C[M,N] = fp16(A)[M,K] @ fp16(W)[K,N].  CTA 128x128, K-tile 32, 3-stage.
#define GT_ROWB   80
#define GT_TILE   (128 * GT_ROWB)          // 10240 B
#define G1_STAGE  (2 * GT_TILE)            // A, B = 20480 B
#define G1_NST    3
#define G1_TOTAL  (G1_NST * G1_STAGE)      // 61440 B -> 2 CTAs/SM

__global__ __launch_bounds__(256, 2)
void gemm_h1(const __half* __restrict__ Ah, const __half* __restrict__ Bh,
             float* __restrict__ C, int Ncols, int K)
{
    extern __shared__ char smc[];
    const uint32_t sbase = smem_to_u32(smc);

    const int tid  = threadIdx.x;
    const int lane = tid & 31;
    const int wid  = tid >> 5;
    const int bx = blockIdx.x;
    const int by = blockIdx.y;
    const int m0 = (wid & 1) * 64;
    const int n0 = (wid >> 1) * 32;

    const int r0c = tid >> 2,          c0c = tid & 3;
    const int r1c = (tid + 256) >> 2;

    const size_t ga0 = (size_t)(by * 128 + r0c) * K + c0c * 8;
    const size_t ga1 = (size_t)(by * 128 + r1c) * K + c0c * 8;
    const size_t gb0 = (size_t)(bx * 128 + r0c) * K + c0c * 8;
    const size_t gb1 = (size_t)(bx * 128 + r1c) * K + c0c * 8;
    const uint32_t so0 = r0c * GT_ROWB + c0c * 16;
    const uint32_t so1 = r1c * GT_ROWB + c0c * 16;

    float acc[4][4][4];
#pragma unroll
    for (int i = 0; i < 4; i++)
#pragma unroll
        for (int j = 0; j < 4; j++)
#pragma unroll
            for (int e = 0; e < 4; e++) acc[i][j][e] = 0.f;

    const int n_kt = K >> 5;

    const uint32_t a_row = (uint32_t)(m0 + (lane & 15));
    const uint32_t a_coloff = (uint32_t)((lane >> 4) * 16);
    const uint32_t b_row = (uint32_t)(n0 + (lane & 7));
    const uint32_t b_coloff = (uint32_t)(((lane >> 3) & 1) * 16);

#define G1LOAD(sidx, ko)                                                   \
    do {                                                                   \
        const uint32_t st_ = sbase + (sidx) * G1_STAGE;                    \
        CP_ASYNC16(st_ + 0 * GT_TILE + so0, Ah + ga0 + (ko));              \
        CP_ASYNC16(st_ + 0 * GT_TILE + so1, Ah + ga1 + (ko));              \
        CP_ASYNC16(st_ + 1 * GT_TILE + so0, Bh + gb0 + (ko));              \
        CP_ASYNC16(st_ + 1 * GT_TILE + so1, Bh + gb1 + (ko));              \
        CP_COMMIT();                                                       \
    } while (0)

    G1LOAD(0, 0);
    G1LOAD(1, 32);

    int sidx = 0;
    for (int kt = 0; kt < n_kt; kt++) {
        if (kt + 1 < n_kt) { CP_WAIT1(); } else { CP_WAIT0(); }
        __syncthreads();
        if (kt + 2 < n_kt) {
            int sn = sidx + 2; if (sn >= G1_NST) sn -= G1_NST;
            G1LOAD(sn, (size_t)(kt + 2) * 32);
        }

        const uint32_t st = sbase + sidx * G1_STAGE;
        const uint32_t sA = st;
        const uint32_t sB = st + GT_TILE;

#pragma unroll
        for (int ks = 0; ks < 2; ks++) {
            const uint32_t kb = ks * 32;
            uint32_t af[4][4], bf[4][2];
#pragma unroll
            for (int mt = 0; mt < 4; mt++)
                ldm_x4(af[mt], sA + (a_row + mt * 16) * GT_ROWB + kb + a_coloff);
#pragma unroll
            for (int nt = 0; nt < 4; nt++)
                ldm_x2(bf[nt], sB + (b_row + nt * 8) * GT_ROWB + kb + b_coloff);
#pragma unroll
            for (int mt = 0; mt < 4; mt++)
#pragma unroll
                for (int nt = 0; nt < 4; nt++)
                    mma16816h(acc[mt][nt], af[mt], bf[nt]);
        }
        sidx++; if (sidx >= G1_NST) sidx -= G1_NST;
    }

    const int g  = lane >> 2;
    const int tg = (lane & 3) * 2;
#pragma unroll
    for (int mt = 0; mt < 4; mt++) {
        const int r = by * 128 + m0 + mt * 16 + g;
#pragma unroll
        for (int nt = 0; nt < 4; nt++) {
            const int cc = bx * 128 + n0 + nt * 8 + tg;
            *(float2*)(C + (size_t)r * Ncols + cc) =
                make_float2(acc[mt][nt][0], acc[mt][nt][1]);
            *(float2*)(C + (size_t)(r + 8) * Ncols + cc) =
                make_float2(acc[mt][nt][2], acc[mt][nt][3]);
        }
    }
}

// ================= fp16 2-pass GEMM (wo — A exact as hi+lo) =================
#define G2_STAGE  (3 * GT_TILE)            // Ah, Al, Bh = 30720 B
#define G2_NST    3
#define G2_TOTAL  (G2_NST * G2_STAGE)      // 92160 B -> 2 CTAs/SM

__global__ __launch_bounds__(256, 2)
void gemm_h2(const __half* __restrict__ Ah, const __half* __restrict__ Al,
             const __half* __restrict__ Bh, float* __restrict__ C, int Ncols, int K)
{
    extern __shared__ char smc[];
    const uint32_t sbase = smem_to_u32(smc);

    const int tid  = threadIdx.x;
    const int lane = tid & 31;
    const int wid  = tid >> 5;
    const int bx = blockIdx.x;
    const int by = blockIdx.y;
    const int m0 = (wid & 1) * 64;
    const int n0 = (wid >> 1) * 32;

    const int r0c = tid >> 2,          c0c = tid & 3;
    const int r1c = (tid + 256) >> 2;

    const size_t ga0 = (size_t)(by * 128 + r0c) * K + c0c * 8;
    const size_t ga1 = (size_t)(by * 128 + r1c) * K + c0c * 8;
    const size_t gb0 = (size_t)(bx * 128 + r0c) * K + c0c * 8;
    const size_t gb1 = (size_t)(bx * 128 + r1c) * K + c0c * 8;
    const uint32_t so0 = r0c * GT_ROWB + c0c * 16;
    const uint32_t so1 = r1c * GT_ROWB + c0c * 16;

    float acc[4][4][4];
#pragma unroll
    for (int i = 0; i < 4; i++)
#pragma unroll
        for (int j = 0; j < 4; j++)
#pragma unroll
            for (int e = 0; e < 4; e++) acc[i][j][e] = 0.f;

    const int n_kt = K >> 5;

    const uint32_t a_row = (uint32_t)(m0 + (lane & 15));
    const uint32_t a_coloff = (uint32_t)((lane >> 4) * 16);
    const uint32_t b_row = (uint32_t)(n0 + (lane & 7));
    const uint32_t b_coloff = (uint32_t)(((lane >> 3) & 1) * 16);

#define G2LOAD(sidx, ko)                                                   \
    do {                                                                   \
        const uint32_t st_ = sbase + (sidx) * G2_STAGE;                    \
        CP_ASYNC16(st_ + 0 * GT_TILE + so0, Ah + ga0 + (ko));              \
        CP_ASYNC16(st_ + 0 * GT_TILE + so1, Ah + ga1 + (ko));              \
        CP_ASYNC16(st_ + 1 * GT_TILE + so0, Al + ga0 + (ko));              \
        CP_ASYNC16(st_ + 1 * GT_TILE + so1, Al + ga1 + (ko));              \
        CP_ASYNC16(st_ + 2 * GT_TILE + so0, Bh + gb0 + (ko));              \
        CP_ASYNC16(st_ + 2 * GT_TILE + so1, Bh + gb1 + (ko));              \
        CP_COMMIT();                                                       \
    } while (0)

    G2LOAD(0, 0);
    G2LOAD(1, 32);

    int sidx = 0;
    for (int kt = 0; kt < n_kt; kt++) {
        if (kt + 1 < n_kt) { CP_WAIT1(); } else { CP_WAIT0(); }
        __syncthreads();
        if (kt + 2 < n_kt) {
            int sn = sidx + 2; if (sn >= G2_NST) sn -= G2_NST;
            G2LOAD(sn, (size_t)(kt + 2) * 32);
        }

        const uint32_t st = sbase + sidx * G2_STAGE;
        const uint32_t sAh = st;
        const uint32_t sAl = st + 1 * GT_TILE;
        const uint32_t sBh = st + 2 * GT_TILE;

#pragma unroll
        for (int ks = 0; ks < 2; ks++) {
            const uint32_t kb = ks * 32;
            uint32_t af[4][4], bf[4][2];
#pragma unroll
            for (int mt = 0; mt < 4; mt++)
                ldm_x4(af[mt], sAh + (a_row + mt * 16) * GT_ROWB + kb + a_coloff);
#pragma unroll
            for (int nt = 0; nt < 4; nt++)
                ldm_x2(bf[nt], sBh + (b_row + nt * 8) * GT_ROWB + kb + b_coloff);
#pragma unroll
            for (int mt = 0; mt < 4; mt++)
#pragma unroll
                for (int nt = 0; nt < 4; nt++)
                    mma16816h(acc[mt][nt], af[mt], bf[nt]);
#pragma unroll
            for (int mt = 0; mt < 4; mt++)
                ldm_x4(af[mt], sAl + (a_row + mt * 16) * GT_ROWB + kb + a_coloff);
#pragma unroll
            for (int mt = 0; mt < 4; mt++)
#pragma unroll
                for (int nt = 0; nt < 4; nt++)
                    mma16816h(acc[mt][nt], af[mt], bf[nt]);
        }
        sidx++; if (sidx >= G2_NST) sidx -= G2_NST;
    }

    const int g  = lane >> 2;
    const int tg = (lane & 3) * 2;
#pragma unroll
    for (int mt = 0; mt < 4; mt++) {
        const int r = by * 128 + m0 + mt * 16 + g;
#pragma unroll
        for (int nt = 0; nt < 4; nt++) {
            const int cc = bx * 128 + n0 + nt * 8 + tg;
            *(float2*)(C + (size_t)r * Ncols + cc) =
                make_float2(acc[mt][nt][0], acc[mt][nt][1]);
            *(float2*)(C + (size_t)(r + 8) * Ncols + cc) =
                make_float2(acc[mt][nt][2], acc[mt][nt][3]);
        }
    }
}

// ---------------- rope table: cos/sin per (pos, pair), computed in double ----------------
__global__ __launch_bounds__(256)
void rope_table()
{
    int idx = blockIdx.x * blockDim.x + threadIdx.x;
    if (idx >= S_LEN * 64) return;
    int pos = idx >> 6, pair = idx & 63;
    double inv = pow(10000.0, -(double)(2 * pair) / 128.0);
    double ang = (double)pos * inv;
    g_rope[idx] = make_float2((float)cos(ang), (float)sin(ang));
}

// ---------------- fp32 -> fp16 ----------------
__global__ __launch_bounds__(256)
void convert_h(const float* __restrict__ X, __half* __restrict__ H, int total)
{
    int i = blockIdx.x * blockDim.x + threadIdx.x;
    if (i >= total) return;
    H[i] = __float2half_rn(X[i]);
}

// ---------------- strided fp32 -> fp16 (V path) ----------------
__global__ __launch_bounds__(256)
void convert_v_h(const float* __restrict__ QKV, __half* __restrict__ V, int total)
{
    int i = blockIdx.x * blockDim.x + threadIdx.x;
    if (i >= total) return;
    int t = i >> 10;
    int c = i & 1023;
    V[i] = __float2half_rn(QKV[(size_t)t * QKV_N + 3072 + c]);
}

// ---------------- W[K,N] -> W^T fp16 [N,K] ----------------
__global__ __launch_bounds__(256)
void transpose_h(const float* __restrict__ W, __half* __restrict__ Th, int K, int N)
{
    __shared__ float t[32][33];
    int n0 = blockIdx.x * 32, k0 = blockIdx.y * 32;
    int tx = threadIdx.x & 31, ty = threadIdx.x >> 5;
#pragma unroll
    for (int j = 0; j < 4; j++)
        t[ty + j * 8][tx] = W[(size_t)(k0 + ty + j * 8) * N + n0 + tx];
    __syncthreads();
#pragma unroll
    for (int j = 0; j < 4; j++)
        Th[(size_t)(n0 + ty + j * 8) * K + k0 + tx] = __float2half_rn(t[tx][ty + j * 8]);
}

// ---------------- RoPE via table ----------------
// q: rotate + scale, write exact fp16 hi/lo
__global__ __launch_bounds__(256)
void rope_q_split(const float* __restrict__ QKV, const int* __restrict__ positions,
                  __half* __restrict__ H, __half* __restrict__ L)
{
    int idx = blockIdx.x * blockDim.x + threadIdx.x;
    if (idx >= T_TOK * NH * 64) return;
    int pair = idx & 63;
    int h    = (idx >> 6) & 15;
    int t    = idx >> 10;
    float2 cs = g_rope[(positions[t] << 6) + pair];
    const float scale = 0.08838834764831845f;
    size_t o_s = (size_t)t * QKV_N + h * HD + 2 * pair;
    size_t o_d = (size_t)t * DIM + h * HD + 2 * pair;
    float xr = QKV[o_s], xi = QKV[o_s + 1];
    float vr = (xr * cs.x - xi * cs.y) * scale;
    float vi = (xr * cs.y + xi * cs.x) * scale;
    __half hr = __float2half_rn(vr);
    __half hh = __float2half_rn(vi);
    H[o_d]     = hr;
    H[o_d + 1] = hh;
    L[o_d]     = __float2half_rn(vr - __half2float(hr));
    L[o_d + 1] = __float2half_rn(vi - __half2float(hh));
}

// k: rotate, write single fp16
__global__ __launch_bounds__(256)
void rope_k_h(const float* __restrict__ QKV, const int* __restrict__ positions,
              __half* __restrict__ Kf)
{
    int idx = blockIdx.x * blockDim.x + threadIdx.x;
    if (idx >= T_TOK * NKV * 64) return;
    int pair = idx & 63;
    int h    = (idx >> 6) & 7;
    int t    = idx >> 9;
    float2 cs = g_rope[(positions[t] << 6) + pair];
    size_t o_s = (size_t)t * QKV_N + 2048 + h * HD + 2 * pair;
    size_t o_d = (size_t)t * KV_DIM + h * HD + 2 * pair;
    float xr = QKV[o_s], xi = QKV[o_s + 1];
    Kf[o_d]     = __float2half_rn(xr * cs.x - xi * cs.y);
    Kf[o_d + 1] = __float2half_rn(xr * cs.y + xi * cs.x);
}

// ================= mma.sync flash attention (causal, GQA rep=2), fp16 2-pass =================
#define AQ_ROWB 272
#define AQ_TILE (128 * AQ_ROWB)        // 34816
#define AKV_TILE (64 * AQ_ROWB)        // 17408
#define AKV_BUF (2 * AKV_TILE)         // 34816 (K + V)
#define AT_SMEM (2 * AQ_TILE + 2 * AKV_BUF)   // 139264 B -> 1 CTA/SM

__global__ __launch_bounds__(256, 1)
void attn_mma(const __half* __restrict__ qh, const __half* __restrict__ ql,
              const __half* __restrict__ kf, const __half* __restrict__ vf,
              __half* __restrict__ oh, __half* __restrict__ ol)
{
    extern __shared__ char smb[];
    const uint32_t sb  = smem_to_u32(smb);
    const uint32_t sQh = sb;
    const uint32_t sQl = sb + AQ_TILE;
    const uint32_t kv0 = sb + 2 * AQ_TILE;

    const int tid  = threadIdx.x;
    const int lane = tid & 31;
    const int wid  = tid >> 5;
    const int qt = blockIdx.x, h = blockIdx.y, b = blockIdx.z;
    const int kvh = h >> 1;
    const int q0 = qt * 128;
    const int m0 = wid * 16;
    const int g  = lane >> 2;
    const int tg = lane & 3;

    {
        const __half* srcH = qh + (size_t)(b * S_LEN + q0) * DIM + h * HD;
        const __half* srcL = ql + (size_t)(b * S_LEN + q0) * DIM + h * HD;
        for (int c = tid; c < 2048; c += 256) {
            int r = c >> 4, cc = c & 15;
            CP_ASYNC16(sQh + r * AQ_ROWB + cc * 16, srcH + (size_t)r * DIM + cc * 8);
            CP_ASYNC16(sQl + r * AQ_ROWB + cc * 16, srcL + (size_t)r * DIM + cc * 8);
        }
        CP_COMMIT();
    }

    const size_t kvbase0 = (size_t)(b * S_LEN) * KV_DIM + kvh * HD;

    {
        const __half* pK = kf + kvbase0;
        const __half* pV = vf + kvbase0;
        for (int c = tid; c < 1024; c += 256) {
            int r = c >> 4, cc = c & 15;
            uint32_t so = r * AQ_ROWB + cc * 16;
            size_t go = (size_t)r * KV_DIM + cc * 8;
            CP_ASYNC16(kv0 + 0 * AKV_TILE + so, pK + go);
            CP_ASYNC16(kv0 + 1 * AKV_TILE + so, pV + go);
        }
        CP_COMMIT();
    }

    float oacc[16][4];
#pragma unroll
    for (int nt = 0; nt < 16; nt++)
#pragma unroll
        for (int e = 0; e < 4; e++) oacc[nt][e] = 0.f;
    float mst0 = -1e30f, mst1 = -1e30f, lst0 = 0.f, lst1 = 0.f;

    const uint32_t qa_off = (uint32_t)((m0 + (lane & 15)) * AQ_ROWB + (lane >> 4) * 16);
    const uint32_t kb_row = (uint32_t)((lane & 7) * AQ_ROWB + ((lane >> 3) & 1) * 16);
    const uint32_t v_row  = (uint32_t)((lane & 15) * AQ_ROWB);

    const int ktmax = 2 * qt + 1;
    for (int kt = 0; kt <= ktmax; kt++) {
        const int cur = kt & 1;
        CP_WAIT0();
        __syncthreads();

        if (kt < ktmax) {
            const uint32_t kvn = kv0 + (cur ^ 1) * AKV_BUF;
            const size_t base = kvbase0 + (size_t)(kt + 1) * 64 * KV_DIM;
            const __half* pK = kf + base;
            const __half* pV = vf + base;
            for (int c = tid; c < 1024; c += 256) {
                int r = c >> 4, cc = c & 15;
                uint32_t so = r * AQ_ROWB + cc * 16;
                size_t go = (size_t)r * KV_DIM + cc * 8;
                CP_ASYNC16(kvn + 0 * AKV_TILE + so, pK + go);
                CP_ASYNC16(kvn + 1 * AKV_TILE + so, pV + go);
            }
            CP_COMMIT();
        }

        const uint32_t sK = kv0 + cur * AKV_BUF;
        const uint32_t sV = sK + AKV_TILE;

        float sacc[8][4];
#pragma unroll
        for (int j = 0; j < 8; j++)
#pragma unroll
            for (int e = 0; e < 4; e++) sacc[j][e] = 0.f;

#pragma unroll
        for (int kk = 0; kk < 8; kk++) {
            uint32_t qfh[4], qfl[4], kfr[2];
            ldm_x4(qfh, sQh + qa_off + kk * 32);
            ldm_x4(qfl, sQl + qa_off + kk * 32);
#pragma unroll
            for (int j = 0; j < 8; j++) {
                ldm_x2(kfr, sK + j * 8 * AQ_ROWB + kb_row + kk * 32);
                mma16816h(sacc[j], qfh, kfr);
                mma16816h(sacc[j], qfl, kfr);
            }
        }

        if (kt * 64 + 63 > q0 + m0 + g) {
            const int r0l = q0 + m0 + g, r1l = r0l + 8;
            const int cb = kt * 64 + tg * 2;
#pragma unroll
            for (int j = 0; j < 8; j++) {
                const int c0 = cb + j * 8;
                if (c0     > r0l) sacc[j][0] = -1e30f;
                if (c0 + 1 > r0l) sacc[j][1] = -1e30f;
                if (c0     > r1l) sacc[j][2] = -1e30f;
                if (c0 + 1 > r1l) sacc[j][3] = -1e30f;
            }
        }

        float mx0 = -1e30f, mx1 = -1e30f;
#pragma unroll
        for (int j = 0; j < 8; j++) {
            mx0 = fmaxf(mx0, fmaxf(sacc[j][0], sacc[j][1]));
            mx1 = fmaxf(mx1, fmaxf(sacc[j][2], sacc[j][3]));
        }
        mx0 = fmaxf(mx0, __shfl_xor_sync(0xffffffffu, mx0, 1));
        mx0 = fmaxf(mx0, __shfl_xor_sync(0xffffffffu, mx0, 2));
        mx1 = fmaxf(mx1, __shfl_xor_sync(0xffffffffu, mx1, 1));
        mx1 = fmaxf(mx1, __shfl_xor_sync(0xffffffffu, mx1, 2));
        const float nm0 = fmaxf(mst0, mx0);
        const float nm1 = fmaxf(mst1, mx1);
        const float a0 = expf(mst0 - nm0);
        const float a1 = expf(mst1 - nm1);
        mst0 = nm0; mst1 = nm1;
        float sum0 = 0.f, sum1 = 0.f;
#pragma unroll
        for (int j = 0; j < 8; j++) {
            sacc[j][0] = expf(sacc[j][0] - nm0);
            sacc[j][1] = expf(sacc[j][1] - nm0);
            sacc[j][2] = expf(sacc[j][2] - nm1);
            sacc[j][3] = expf(sacc[j][3] - nm1);
            sum0 += sacc[j][0] + sacc[j][1];
            sum1 += sacc[j][2] + sacc[j][3];
        }
        sum0 += __shfl_xor_sync(0xffffffffu, sum0, 1);
        sum0 += __shfl_xor_sync(0xffffffffu, sum0, 2);
        sum1 += __shfl_xor_sync(0xffffffffu, sum1, 1);
        sum1 += __shfl_xor_sync(0xffffffffu, sum1, 2);
        lst0 = lst0 * a0 + sum0;
        lst1 = lst1 * a1 + sum1;
#pragma unroll
        for (int nt = 0; nt < 16; nt++) {
            oacc[nt][0] *= a0; oacc[nt][1] *= a0;
            oacc[nt][2] *= a1; oacc[nt][3] *= a1;
        }

#pragma unroll
        for (int jk = 0; jk < 4; jk++) {
            uint32_t pfh[4], pfl[4];
#pragma unroll
            for (int q = 0; q < 2; q++) {
                const int j = 2 * jk + q;
#pragma unroll
                for (int pr = 0; pr < 2; pr++) {
                    float p0 = sacc[j][2 * pr], p1 = sacc[j][2 * pr + 1];
                    __half b0 = __float2half_rn(p0);
                    __half b1 = __float2half_rn(p1);
                    { __half2 t2 = __halves2half2(b0, b1); pfh[2 * q + pr] = *(uint32_t*)&t2; }
                    pfl[2 * q + pr] = packh(p0 - __half2float(b0),
                                            p1 - __half2float(b1));
                }
            }
            const uint32_t vbase = jk * 16 * AQ_ROWB + v_row;
#pragma unroll
            for (int nt = 0; nt < 16; nt++) {
                uint32_t vfr[2];
                ldm_x2_trans(vfr, sV + vbase + nt * 16);
                mma16816h(oacc[nt], pfh, vfr);
                mma16816h(oacc[nt], pfl, vfr);
            }
        }
    }

    const float inv0 = 1.f / lst0;
    const float inv1 = 1.f / lst1;
    const size_t r0g = (size_t)(b * S_LEN + q0 + m0 + g);
    const size_t r1g = r0g + 8;
    const int colb = h * HD + tg * 2;
#pragma unroll
    for (int nt = 0; nt < 16; nt++) {
        float v00 = oacc[nt][0] * inv0, v01 = oacc[nt][1] * inv0;
        float v10 = oacc[nt][2] * inv1, v11 = oacc[nt][3] * inv1;
        __half h00 = __float2half_rn(v00), h01 = __float2half_rn(v01);
        __half h10 = __float2half_rn(v10), h11 = __float2half_rn(v11);
        uint32_t hw0, hw1;
        { __half2 t2 = __halves2half2(h00, h01); hw0 = *(uint32_t*)&t2; }
        { __half2 t2 = __halves2half2(h10, h11); hw1 = *(uint32_t*)&t2; }
        uint32_t lw0 = packh(v00 - __half2float(h00), v01 - __half2float(h01));
        uint32_t lw1 = packh(v10 - __half2float(h10), v11 - __half2float(h11));
        const int cc = colb + nt * 8;
        *(uint32_t*)(oh + r0g * DIM + cc) = hw0;
        *(uint32_t*)(ol + r0g * DIM + cc) = lw0;
        *(uint32_t*)(oh + r1g * DIM + cc) = hw1;
        *(uint32_t*)(ol + r1g * DIM + cc) = lw1;
    }
}

// ---------------- launcher ----------------
extern "C" void kernel_launch(void* const* d_in, const int* in_sizes, int n_in,
                              void* d_out, int out_size)
{
    const float* x  = (const float*)d_in[0];
    const float* wq = (const float*)d_in[1];
    const float* wk = (const float*)d_in[2];
    const float* wv = (const float*)d_in[3];
    const float* wo = (const float*)d_in[4];
    const int* positions = (const int*)d_in[7];
    float* out = (float*)d_out;

    float* pqkv;
    cudaGetSymbolAddress((void**)&pqkv, g_qkv);

    __half *xf, *ah, *al, *wqkvT, *woT, *qbh, *qbl, *pkf, *pvf;
    cudaGetSymbolAddress((void**)&xf, g_xf);
    cudaGetSymbolAddress((void**)&ah, g_ah);
    cudaGetSymbolAddress((void**)&al, g_al);
    cudaGetSymbolAddress((void**)&wqkvT, g_wqkvT);
    cudaGetSymbolAddress((void**)&woT, g_woT);
    cudaGetSymbolAddress((void**)&qbh, g_qbh);
    cudaGetSymbolAddress((void**)&qbl, g_qbl);
    cudaGetSymbolAddress((void**)&pkf, g_kf);
    cudaGetSymbolAddress((void**)&pvf, g_vf);

    cudaFuncSetAttribute(gemm_h1,  cudaFuncAttributeMaxDynamicSharedMemorySize, G1_TOTAL);
    cudaFuncSetAttribute(gemm_h2,  cudaFuncAttributeMaxDynamicSharedMemorySize, G2_TOTAL);
    cudaFuncSetAttribute(attn_mma, cudaFuncAttributeMaxDynamicSharedMemorySize, AT_SMEM);

    // 1: rope table
    rope_table<<<(S_LEN * 64 + 255) / 256, 256>>>();
    // 2: x -> fp16
    {
        int total = T_TOK * DIM;
        convert_h<<<(total + 255) / 256, 256>>>(x, xf, total);
    }
    // 3-5: weight transposes into concatenated wqkv^T
    transpose_h<<<dim3(DIM / 32,    DIM / 32), 256>>>(wq, wqkvT,              DIM, DIM);
    transpose_h<<<dim3(KV_DIM / 32, DIM / 32), 256>>>(wk, wqkvT + 2048 * DIM, DIM, KV_DIM);
    transpose_h<<<dim3(KV_DIM / 32, DIM / 32), 256>>>(wv, wqkvT + 3072 * DIM, DIM, KV_DIM);
    // 6: fused QKV GEMM (single-pass fp16)  <- ncu -s 5 -c 1 captures this
    gemm_h1<<<dim3(QKV_N / 128, T_TOK / 128), 256, G1_TOTAL>>>(xf, wqkvT, pqkv, QKV_N, DIM);
    // 7: wo transpose
    transpose_h<<<dim3(DIM / 32, DIM / 32), 256>>>(wo, woT, DIM, DIM);
    // 8-10: RoPE + converts (table-based, no fp64)
    {
        int total_q = T_TOK * NH * 64;
        int total_k = T_TOK * NKV * 64;
        rope_q_split<<<(total_q + 255) / 256, 256>>>(pqkv, positions, qbh, qbl);
        rope_k_h<<<(total_k + 255) / 256, 256>>>(pqkv, positions, pkf);
        int total_v = T_TOK * KV_DIM;
        convert_v_h<<<(total_v + 255) / 256, 256>>>(pqkv, pvf, total_v);
    }
    // 11: flash attention
    attn_mma<<<dim3(S_LEN / 128, NH, B_SZ), 256, AT_SMEM>>>(qbh, qbl, pkf, pvf, ah, al);
    // 12: output projection (exact-A 2-pass)
    gemm_h2<<<dim3(DIM / 128, T_TOK / 128), 256, G2_TOTAL>>>(ah, al, woT, out, DIM, DIM);
}

// round 12
// speedup vs baseline: 4.1986x; 1.1550x over previous
#include <cuda_runtime.h>
#include <cuda_bf16.h>
#include <cuda_fp16.h>
#include <cstdint>
#include <math.h>

// ---------------- problem constants ----------------
#define T_TOK   8192
#define DIM     2048
#define NH      16
#define NKV     8
#define HD      128
#define S_LEN   1024
#define B_SZ    8
#define KV_DIM  1024      // NKV * HD
#define QKV_N   4096      // DIM + 2*KV_DIM

// ---------------- scratch ----------------
__device__ float g_qkv[T_TOK * QKV_N];     // fused QKV GEMM output

__device__ float2 g_rope[S_LEN * 64];      // cos/sin per (pos, pair)

// fp16 activations
__device__ __half g_xf[T_TOK * DIM];       // x single fp16 (QKV gemm A)
__device__ __half g_af[T_TOK * DIM];       // attn out single fp16 (wo gemm A)
// fp16 transposed weights [N,K]
__device__ __half g_wqkvT[QKV_N * DIM];    // rows: 0-2047 wq^T, 2048-3071 wk^T, 3072-4095 wv^T
__device__ __half g_woT[DIM * DIM];
// fp16 attention operands
__device__ __half g_qbh[T_TOK * DIM];      // q hi (exact split with g_qbl)
__device__ __half g_qbl[T_TOK * DIM];
__device__ __half g_kf[T_TOK * KV_DIM];    // k single fp16
__device__ __half g_vf[T_TOK * KV_DIM];    // v single fp16

// ================= low-level helpers (sm_80-class PTX only) =================
__device__ __forceinline__ uint32_t smem_to_u32(const void* smem_ptr) {
    uint32_t addr;
    asm("{ .reg .u64 tmp; cvta.to.shared.u64 tmp, %1; cvt.u32.u64 %0, tmp; }"
        : "=r"(addr) : "l"(smem_ptr));
    return addr;
}

#define CP_ASYNC16(dst_u32, src_ptr) \
    asm volatile("cp.async.cg.shared.global [%0], [%1], 16;" \
                 :: "r"(dst_u32), "l"(src_ptr) : "memory")
#define CP_COMMIT() asm volatile("cp.async.commit_group;" ::: "memory")
#define CP_WAIT0()  asm volatile("cp.async.wait_group 0;" ::: "memory")
#define CP_WAIT1()  asm volatile("cp.async.wait_group 1;" ::: "memory")

__device__ __forceinline__ void ldm_x4(uint32_t* r, uint32_t addr) {
    asm volatile("ldmatrix.sync.aligned.m8n8.x4.shared.b16 {%0,%1,%2,%3}, [%4];"
                 : "=r"(r[0]), "=r"(r[1]), "=r"(r[2]), "=r"(r[3]) : "r"(addr));
}
__device__ __forceinline__ void ldm_x2(uint32_t* r, uint32_t addr) {
    asm volatile("ldmatrix.sync.aligned.m8n8.x2.shared.b16 {%0,%1}, [%2];"
                 : "=r"(r[0]), "=r"(r[1]) : "r"(addr));
}
__device__ __forceinline__ void ldm_x2_trans(uint32_t* r, uint32_t addr) {
    asm volatile("ldmatrix.sync.aligned.m8n8.x2.trans.shared.b16 {%0,%1}, [%2];"
                 : "=r"(r[0]), "=r"(r[1]) : "r"(addr));
}
// fp16 mma
__device__ __forceinline__ void mma16816h(float* c, const uint32_t* a, const uint32_t* b) {
    asm volatile("mma.sync.aligned.m16n8k16.row.col.f32.f16.f16.f32 "
                 "{%0,%1,%2,%3}, {%4,%5,%6,%7}, {%8,%9}, {%0,%1,%2,%3};"
                 : "+f"(c[0]), "+f"(c[1]), "+f"(c[2]), "+f"(c[3])
                 : "r"(a[0]), "r"(a[1]), "r"(a[2]), "r"(a[3]), "r"(b[0]), "r"(b[1]));
}
__device__ __forceinline__ uint32_t packh(float lo, float hi) {
    __half2 h = __floats2half2_rn(lo, hi);
    return *(uint32_t*)&h;
}

// ================= fp16 single-pass GEMM (QKV and wo) =================
// C[M,N] = fp16(A)[M,K] @ fp16(W)[K,N].  CTA 128x128, K-tile 32, 3-stage.
#define GT_ROWB   80
#define GT_TILE   (128 * GT_ROWB)          // 10240 B
#define G1_STAGE  (2 * GT_TILE)            // A, B = 20480 B
#define G1_NST    3
#define G1_TOTAL  (G1_NST * G1_STAGE)      // 61440 B -> 2 CTAs/SM

__global__ __launch_bounds__(256, 2)
void gemm_h1(const __half* __restrict__ Ah, const __half* __restrict__ Bh,
             float* __restrict__ C, int Ncols, int K)
{
    extern __shared__ char smc[];
    const uint32_t sbase = smem_to_u32(smc);

    const int tid  = threadIdx.x;
    const int lane = tid & 31;
    const int wid  = tid >> 5;
    const int bx = blockIdx.x;
    const int by = blockIdx.y;
    const int m0 = (wid & 1) * 64;
    const int n0 = (wid >> 1) * 32;

    const int r0c = tid >> 2,          c0c = tid & 3;
    const int r1c = (tid + 256) >> 2;

    const size_t ga0 = (size_t)(by * 128 + r0c) * K + c0c * 8;
    const size_t ga1 = (size_t)(by * 128 + r1c) * K + c0c * 8;
    const size_t gb0 = (size_t)(bx * 128 + r0c) * K + c0c * 8;
    const size_t gb1 = (size_t)(bx * 128 + r1c) * K + c0c * 8;
    const uint32_t so0 = r0c * GT_ROWB + c0c * 16;
    const uint32_t so1 = r1c * GT_ROWB + c0c * 16;

    float acc[4][4][4];
#pragma unroll
    for (int i = 0; i < 4; i++)
#pragma unroll
        for (int j = 0; j < 4; j++)
#pragma unroll
            for (int e = 0; e < 4; e++) acc[i][j][e] = 0.f;

    const int n_kt = K >> 5;

    const uint32_t a_row = (uint32_t)(m0 + (lane & 15));
    const uint32_t a_coloff = (uint32_t)((lane >> 4) * 16);
    const uint32_t b_row = (uint32_t)(n0 + (lane & 7));
    const uint32_t b_coloff = (uint32_t)(((lane >> 3) & 1) * 16);

#define G1LOAD(sidx, ko)                                                   \
    do {                                                                   \
        const uint32_t st_ = sbase + (sidx) * G1_STAGE;                    \
        CP_ASYNC16(st_ + 0 * GT_TILE + so0, Ah + ga0 + (ko));              \
        CP_ASYNC16(st_ + 0 * GT_TILE + so1, Ah + ga1 + (ko));              \
        CP_ASYNC16(st_ + 1 * GT_TILE + so0, Bh + gb0 + (ko));              \
        CP_ASYNC16(st_ + 1 * GT_TILE + so1, Bh + gb1 + (ko));              \
        CP_COMMIT();                                                       \
    } while (0)

    G1LOAD(0, 0);
    G1LOAD(1, 32);

    int sidx = 0;
    for (int kt = 0; kt < n_kt; kt++) {
        if (kt + 1 < n_kt) { CP_WAIT1(); } else { CP_WAIT0(); }
        __syncthreads();
        if (kt + 2 < n_kt) {
            int sn = sidx + 2; if (sn >= G1_NST) sn -= G1_NST;
            G1LOAD(sn, (size_t)(kt + 2) * 32);
        }

        const uint32_t st = sbase + sidx * G1_STAGE;
        const uint32_t sA = st;
        const uint32_t sB = st + GT_TILE;

#pragma unroll
        for (int ks = 0; ks < 2; ks++) {
            const uint32_t kb = ks * 32;
            uint32_t af[4][4], bf[4][2];
#pragma unroll
            for (int mt = 0; mt < 4; mt++)
                ldm_x4(af[mt], sA + (a_row + mt * 16) * GT_ROWB + kb + a_coloff);
#pragma unroll
            for (int nt = 0; nt < 4; nt++)
                ldm_x2(bf[nt], sB + (b_row + nt * 8) * GT_ROWB + kb + b_coloff);
#pragma unroll
            for (int mt = 0; mt < 4; mt++)
#pragma unroll
                for (int nt = 0; nt < 4; nt++)
                    mma16816h(acc[mt][nt], af[mt], bf[nt]);
        }
        sidx++; if (sidx >= G1_NST) sidx -= G1_NST;
    }

    const int g  = lane >> 2;
    const int tg = (lane & 3) * 2;
#pragma unroll
    for (int mt = 0; mt < 4; mt++) {
        const int r = by * 128 + m0 + mt * 16 + g;
#pragma unroll
        for (int nt = 0; nt < 4; nt++) {
            const int cc = bx * 128 + n0 + nt * 8 + tg;
            *(float2*)(C + (size_t)r * Ncols + cc) =
                make_float2(acc[mt][nt][0], acc[mt][nt][1]);
            *(float2*)(C + (size_t)(r + 8) * Ncols + cc) =
                make_float2(acc[mt][nt][2], acc[mt][nt][3]);
        }
    }
}

// ---------------- rope table: cos/sin per (pos, pair), computed in double ----------------
__global__ __launch_bounds__(256)
void rope_table()
{
    int idx = blockIdx.x * blockDim.x + threadIdx.x;
    if (idx >= S_LEN * 64) return;
    int pos = idx >> 6, pair = idx & 63;
    double inv = pow(10000.0, -(double)(2 * pair) / 128.0);
    double ang = (double)pos * inv;
    g_rope[idx] = make_float2((float)cos(ang), (float)sin(ang));
}

// ---------------- fp32 -> fp16 ----------------
__global__ __launch_bounds__(256)
void convert_h(const float* __restrict__ X, __half* __restrict__ H, int total)
{
    int i = blockIdx.x * blockDim.x + threadIdx.x;
    if (i >= total) return;
    H[i] = __float2half_rn(X[i]);
}

// ---------------- strided fp32 -> fp16 (V path) ----------------
__global__ __launch_bounds__(256)
void convert_v_h(const float* __restrict__ QKV, __half* __restrict__ V, int total)
{
    int i = blockIdx.x * blockDim.x + threadIdx.x;
    if (i >= total) return;
    int t = i >> 10;
    int c = i & 1023;
    V[i] = __float2half_rn(QKV[(size_t)t * QKV_N + 3072 + c]);
}

// ---------------- W[K,N] -> W^T fp16 [N,K] ----------------
__global__ __launch_bounds__(256)
void transpose_h(const float* __restrict__ W, __half* __restrict__ Th, int K, int N)
{
    __shared__ float t[32][33];
    int n0 = blockIdx.x * 32, k0 = blockIdx.y * 32;
    int tx = threadIdx.x & 31, ty = threadIdx.x >> 5;
#pragma unroll
    for (int j = 0; j < 4; j++)
        t[ty + j * 8][tx] = W[(size_t)(k0 + ty + j * 8) * N + n0 + tx];
    __syncthreads();
#pragma unroll
    for (int j = 0; j < 4; j++)
        Th[(size_t)(n0 + ty + j * 8) * K + k0 + tx] = __float2half_rn(t[tx][ty + j * 8]);
}

// ---------------- RoPE via table ----------------
// q: rotate + scale, write exact fp16 hi/lo
__global__ __launch_bounds__(256)
void rope_q_split(const float* __restrict__ QKV, const int* __restrict__ positions,
                  __half* __restrict__ H, __half* __restrict__ L)
{
    int idx = blockIdx.x * blockDim.x + threadIdx.x;
    if (idx >= T_TOK * NH * 64) return;
    int pair = idx & 63;
    int h    = (idx >> 6) & 15;
    int t    = idx >> 10;
    float2 cs = g_rope[(positions[t] << 6) + pair];
    const float scale = 0.08838834764831845f;
    size_t o_s = (size_t)t * QKV_N + h * HD + 2 * pair;
    size_t o_d = (size_t)t * DIM + h * HD + 2 * pair;
    float xr = QKV[o_s], xi = QKV[o_s + 1];
    float vr = (xr * cs.x - xi * cs.y) * scale;
    float vi = (xr * cs.y + xi * cs.x) * scale;
    __half hr = __float2half_rn(vr);
    __half hh = __float2half_rn(vi);
    H[o_d]     = hr;
    H[o_d + 1] = hh;
    L[o_d]     = __float2half_rn(vr - __half2float(hr));
    L[o_d + 1] = __float2half_rn(vi - __half2float(hh));
}

// k: rotate, write single fp16
__global__ __launch_bounds__(256)
void rope_k_h(const float* __restrict__ QKV, const int* __restrict__ positions,
              __half* __restrict__ Kf)
{
    int idx = blockIdx.x * blockDim.x + threadIdx.x;
    if (idx >= T_TOK * NKV * 64) return;
    int pair = idx & 63;
    int h    = (idx >> 6) & 7;
    int t    = idx >> 9;
    float2 cs = g_rope[(positions[t] << 6) + pair];
    size_t o_s = (size_t)t * QKV_N + 2048 + h * HD + 2 * pair;
    size_t o_d = (size_t)t * KV_DIM + h * HD + 2 * pair;
    float xr = QKV[o_s], xi = QKV[o_s + 1];
    Kf[o_d]     = __float2half_rn(xr * cs.x - xi * cs.y);
    Kf[o_d + 1] = __float2half_rn(xr * cs.y + xi * cs.x);
}

// ================= mma.sync flash attention (causal, GQA rep=2), fp16 2-pass =================
#define AQ_ROWB 272
#define AQ_TILE (128 * AQ_ROWB)        // 34816
#define AKV_TILE (64 * AQ_ROWB)        // 17408
#define AKV_BUF (2 * AKV_TILE)         // 34816 (K + V)
#define AT_SMEM (2 * AQ_TILE + 2 * AKV_BUF)   // 139264 B -> 1 CTA/SM

__global__ __launch_bounds__(256, 1)
void attn_mma(const __half* __restrict__ qh, const __half* __restrict__ ql,
              const __half* __restrict__ kf, const __half* __restrict__ vf,
              __half* __restrict__ oh)
{
    extern __shared__ char smb[];
    const uint32_t sb  = smem_to_u32(smb);
    const uint32_t sQh = sb;
    const uint32_t sQl = sb + AQ_TILE;
    const uint32_t kv0 = sb + 2 * AQ_TILE;

    const int tid  = threadIdx.x;
    const int lane = tid & 31;
    const int wid  = tid >> 5;
    const int qt = blockIdx.x, h = blockIdx.y, b = blockIdx.z;
    const int kvh = h >> 1;
    const int q0 = qt * 128;
    const int m0 = wid * 16;
    const int g  = lane >> 2;
    const int tg = lane & 3;

    {
        const __half* srcH = qh + (size_t)(b * S_LEN + q0) * DIM + h * HD;
        const __half* srcL = ql + (size_t)(b * S_LEN + q0) * DIM + h * HD;
        for (int c = tid; c < 2048; c += 256) {
            int r = c >> 4, cc = c & 15;
            CP_ASYNC16(sQh + r * AQ_ROWB + cc * 16, srcH + (size_t)r * DIM + cc * 8);
            CP_ASYNC16(sQl + r * AQ_ROWB + cc * 16, srcL + (size_t)r * DIM + cc * 8);
        }
        CP_COMMIT();
    }

    const size_t kvbase0 = (size_t)(b * S_LEN) * KV_DIM + kvh * HD;

    {
        const __half* pK = kf + kvbase0;
        const __half* pV = vf + kvbase0;
        for (int c = tid; c < 1024; c += 256) {
            int r = c >> 4, cc = c & 15;
            uint32_t so = r * AQ_ROWB + cc * 16;
            size_t go = (size_t)r * KV_DIM + cc * 8;
            CP_ASYNC16(kv0 + 0 * AKV_TILE + so, pK + go);
            CP_ASYNC16(kv0 + 1 * AKV_TILE + so, pV + go);
        }
        CP_COMMIT();
    }

    float oacc[16][4];
#pragma unroll
    for (int nt = 0; nt < 16; nt++)
#pragma unroll
        for (int e = 0; e < 4; e++) oacc[nt][e] = 0.f;
    float mst0 = -1e30f, mst1 = -1e30f, lst0 = 0.f, lst1 = 0.f;

    const uint32_t qa_off = (uint32_t)((m0 + (lane & 15)) * AQ_ROWB + (lane >> 4) * 16);
    const uint32_t kb_row = (uint32_t)((lane & 7) * AQ_ROWB + ((lane >> 3) & 1) * 16);
    const uint32_t v_row  = (uint32_t)((lane & 15) * AQ_ROWB);

    const int ktmax = 2 * qt + 1;
    for (int kt = 0; kt <= ktmax; kt++) {
        const int cur = kt & 1;
        CP_WAIT0();
        __syncthreads();

        if (kt < ktmax) {
            const uint32_t kvn = kv0 + (cur ^ 1) * AKV_BUF;
            const size_t base = kvbase0 + (size_t)(kt + 1) * 64 * KV_DIM;
            const __half* pK = kf + base;
            const __half* pV = vf + base;
            for (int c = tid; c < 1024; c += 256) {
                int r = c >> 4, cc = c & 15;
                uint32_t so = r * AQ_ROWB + cc * 16;
                size_t go = (size_t)r * KV_DIM + cc * 8;
                CP_ASYNC16(kvn + 0 * AKV_TILE + so, pK + go);
                CP_ASYNC16(kvn + 1 * AKV_TILE + so, pV + go);
            }
            CP_COMMIT();
        }

        const uint32_t sK = kv0 + cur * AKV_BUF;
        const uint32_t sV = sK + AKV_TILE;

        float sacc[8][4];
#pragma unroll
        for (int j = 0; j < 8; j++)
#pragma unroll
            for (int e = 0; e < 4; e++) sacc[j][e] = 0.f;

#pragma unroll
        for (int kk = 0; kk < 8; kk++) {
            uint32_t qfh[4], qfl[4], kfr[2];
            ldm_x4(qfh, sQh + qa_off + kk * 32);
            ldm_x4(qfl, sQl + qa_off + kk * 32);
#pragma unroll
            for (int j = 0; j < 8; j++) {
                ldm_x2(kfr, sK + j * 8 * AQ_ROWB + kb_row + kk * 32);
                mma16816h(sacc[j], qfh, kfr);
                mma16816h(sacc[j], qfl, kfr);
            }
        }

        if (kt * 64 + 63 > q0 + m0 + g) {
            const int r0l = q0 + m0 + g, r1l = r0l + 8;
            const int cb = kt * 64 + tg * 2;
#pragma unroll
            for (int j = 0; j < 8; j++) {
                const int c0 = cb + j * 8;
                if (c0     > r0l) sacc[j][0] = -1e30f;
                if (c0 + 1 > r0l) sacc[j][1] = -1e30f;
                if (c0     > r1l) sacc[j][2] = -1e30f;
                if (c0 + 1 > r1l) sacc[j][3] = -1e30f;
            }
        }

        float mx0 = -1e30f, mx1 = -1e30f;
#pragma unroll
        for (int j = 0; j < 8; j++) {
            mx0 = fmaxf(mx0, fmaxf(sacc[j][0], sacc[j][1]));
            mx1 = fmaxf(mx1, fmaxf(sacc[j][2], sacc[j][3]));
        }
        mx0 = fmaxf(mx0, __shfl_xor_sync(0xffffffffu, mx0, 1));
        mx0 = fmaxf(mx0, __shfl_xor_sync(0xffffffffu, mx0, 2));
        mx1 = fmaxf(mx1, __shfl_xor_sync(0xffffffffu, mx1, 1));
        mx1 = fmaxf(mx1, __shfl_xor_sync(0xffffffffu, mx1, 2));
        const float nm0 = fmaxf(mst0, mx0);
        const float nm1 = fmaxf(mst1, mx1);
        const float a0 = expf(mst0 - nm0);
        const float a1 = expf(mst1 - nm1);
        mst0 = nm0; mst1 = nm1;
        float sum0 = 0.f, sum1 = 0.f;
#pragma unroll
        for (int j = 0; j < 8; j++) {
            sacc[j][0] = expf(sacc[j][0] - nm0);
            sacc[j][1] = expf(sacc[j][1] - nm0);
            sacc[j][2] = expf(sacc[j][2] - nm1);
            sacc[j][3] = expf(sacc[j][3] - nm1);
            sum0 += sacc[j][0] + sacc[j][1];
            sum1 += sacc[j][2] + sacc[j][3];
        }
        sum0 += __shfl_xor_sync(0xffffffffu, sum0, 1);
        sum0 += __shfl_xor_sync(0xffffffffu, sum0, 2);
        sum1 += __shfl_xor_sync(0xffffffffu, sum1, 1);
        sum1 += __shfl_xor_sync(0xffffffffu, sum1, 2);
        lst0 = lst0 * a0 + sum0;
        lst1 = lst1 * a1 + sum1;
#pragma unroll
        for (int nt = 0; nt < 16; nt++) {
            oacc[nt][0] *= a0; oacc[nt][1] *= a0;
            oacc[nt][2] *= a1; oacc[nt][3] *= a1;
        }

#pragma unroll
        for (int jk = 0; jk < 4; jk++) {
            uint32_t pfh[4], pfl[4];
#pragma unroll
            for (int q = 0; q < 2; q++) {
                const int j = 2 * jk + q;
#pragma unroll
                for (int pr = 0; pr < 2; pr++) {
                    float p0 = sacc[j][2 * pr], p1 = sacc[j][2 * pr + 1];
                    __half b0 = __float2half_rn(p0);
                    __half b1 = __float2half_rn(p1);
                    { __half2 t2 = __halves2half2(b0, b1); pfh[2 * q + pr] = *(uint32_t*)&t2; }
                    pfl[2 * q + pr] = packh(p0 - __half2float(b0),
                                            p1 - __half2float(b1));
                }
            }
            const uint32_t vbase = jk * 16 * AQ_ROWB + v_row;
#pragma unroll
            for (int nt = 0; nt < 16; nt++) {
                uint32_t vfr[2];
                ldm_x2_trans(vfr, sV + vbase + nt * 16);
                mma16816h(oacc[nt], pfh, vfr);
                mma16816h(oacc[nt], pfl, vfr);
            }
        }
    }

    // --- epilogue: normalize, store single fp16 ---
    const float inv0 = 1.f / lst0;
    const float inv1 = 1.f / lst1;
    const size_t r0g = (size_t)(b * S_LEN + q0 + m0 + g);
    const size_t r1g = r0g + 8;
    const int colb = h * HD + tg * 2;
#pragma unroll
    for (int nt = 0; nt < 16; nt++) {
        uint32_t hw0 = packh(oacc[nt][0] * inv0, oacc[nt][1] * inv0);
        uint32_t hw1 = packh(oacc[nt][2] * inv1, oacc[nt][3] * inv1);
        const int cc = colb + nt * 8;
        *(uint32_t*)(oh + r0g * DIM + cc) = hw0;
        *(uint32_t*)(oh + r1g * DIM + cc) = hw1;
    }
}

// ---------------- launcher ----------------
extern "C" void kernel_launch(void* const* d_in, const int* in_sizes, int n_in,
                              void* d_out, int out_size)
{
    const float* x  = (const float*)d_in[0];
    const float* wq = (const float*)d_in[1];
    const float* wk = (const float*)d_in[2];
    const float* wv = (const float*)d_in[3];
    const float* wo = (const float*)d_in[4];
    const int* positions = (const int*)d_in[7];
    float* out = (float*)d_out;

    float* pqkv;
    cudaGetSymbolAddress((void**)&pqkv, g_qkv);

    __half *xf, *af, *wqkvT, *woT, *qbh, *qbl, *pkf, *pvf;
    cudaGetSymbolAddress((void**)&xf, g_xf);
    cudaGetSymbolAddress((void**)&af, g_af);
    cudaGetSymbolAddress((void**)&wqkvT, g_wqkvT);
    cudaGetSymbolAddress((void**)&woT, g_woT);
    cudaGetSymbolAddress((void**)&qbh, g_qbh);
    cudaGetSymbolAddress((void**)&qbl, g_qbl);
    cudaGetSymbolAddress((void**)&pkf, g_kf);
    cudaGetSymbolAddress((void**)&pvf, g_vf);

    cudaFuncSetAttribute(gemm_h1,  cudaFuncAttributeMaxDynamicSharedMemorySize, G1_TOTAL);
    cudaFuncSetAttribute(attn_mma, cudaFuncAttributeMaxDynamicSharedMemorySize, AT_SMEM);

    // 1: rope table
    rope_table<<<(S_LEN * 64 + 255) / 256, 256>>>();
    // 2: x -> fp16
    {
        int total = T_TOK * DIM;
        convert_h<<<(total + 255) / 256, 256>>>(x, xf, total);
    }
    // 3-5: weight transposes into concatenated wqkv^T
    transpose_h<<<dim3(DIM / 32,    DIM / 32), 256>>>(wq, wqkvT,              DIM, DIM);
    transpose_h<<<dim3(KV_DIM / 32, DIM / 32), 256>>>(wk, wqkvT + 2048 * DIM, DIM, KV_DIM);
    transpose_h<<<dim3(KV_DIM / 32, DIM / 32), 256>>>(wv, wqkvT + 3072 * DIM, DIM, KV_DIM);
    // 6: fused QKV GEMM (single-pass fp16)
    gemm_h1<<<dim3(QKV_N / 128, T_TOK / 128), 256, G1_TOTAL>>>(xf, wqkvT, pqkv, QKV_N, DIM);
    // 7: wo transpose
    transpose_h<<<dim3(DIM / 32, DIM / 32), 256>>>(wo, woT, DIM, DIM);
    // 8-10: RoPE + converts (table-based, no fp64)
    {
        int total_q = T_TOK * NH * 64;
        int total_k = T_TOK * NKV * 64;
        rope_q_split<<<(total_q + 255) / 256, 256>>>(pqkv, positions, qbh, qbl);
        rope_k_h<<<(total_k + 255) / 256, 256>>>(pqkv, positions, pkf);
        int total_v = T_TOK * KV_DIM;
        convert_v_h<<<(total_v + 255) / 256, 256>>>(pqkv, pvf, total_v);
    }
    // 11: flash attention (single fp16 output)
    attn_mma<<<dim3(S_LEN / 128, NH, B_SZ), 256, AT_SMEM>>>(qbh, qbl, pkf, pvf, af);
    // 12: output projection (single-pass fp16)
    gemm_h1<<<dim3(DIM / 128, T_TOK / 128), 256, G1_TOTAL>>>(af, woT, out, DIM, DIM);
}

// round 13
// speedup vs baseline: 4.6411x; 1.1054x over previous
#include <cuda_runtime.h>
#include <cuda_bf16.h>
#include <cuda_fp16.h>
#include <cstdint>
#include <math.h>

// ---------------- problem constants ----------------
#define T_TOK   8192
#define DIM     2048
#define NH      16
#define NKV     8
#define HD      128
#define S_LEN   1024
#define B_SZ    8
#define KV_DIM  1024      // NKV * HD
#define QKV_N   4096      // DIM + 2*KV_DIM

// ---------------- scratch ----------------
__device__ float2 g_rope[S_LEN * 64];      // cos/sin per (pos, pair)

// fp16 activations
__device__ __half g_xf[T_TOK * DIM];       // x single fp16 (QKV gemm A)
__device__ __half g_af[T_TOK * DIM];       // attn out single fp16 (wo gemm A)
// fp16 transposed weights [N,K]
__device__ __half g_wqkvT[QKV_N * DIM];    // rows: 0-2047 wq^T, 2048-3071 wk^T, 3072-4095 wv^T
__device__ __half g_woT[DIM * DIM];
// fp16 attention operands (written by fused QKV gemm epilogue)
__device__ __half g_qf[T_TOK * DIM];       // q (roped, scaled) fp16
__device__ __half g_kf[T_TOK * KV_DIM];    // k (roped) fp16
__device__ __half g_vf[T_TOK * KV_DIM];    // v fp16

// ================= low-level helpers (sm_80-class PTX only) =================
__device__ __forceinline__ uint32_t smem_to_u32(const void* smem_ptr) {
    uint32_t addr;
    asm("{ .reg .u64 tmp; cvta.to.shared.u64 tmp, %1; cvt.u32.u64 %0, tmp; }"
        : "=r"(addr) : "l"(smem_ptr));
    return addr;
}

#define CP_ASYNC16(dst_u32, src_ptr) \
    asm volatile("cp.async.cg.shared.global [%0], [%1], 16;" \
                 :: "r"(dst_u32), "l"(src_ptr) : "memory")
#define CP_COMMIT() asm volatile("cp.async.commit_group;" ::: "memory")
#define CP_WAIT0()  asm volatile("cp.async.wait_group 0;" ::: "memory")
#define CP_WAIT1()  asm volatile("cp.async.wait_group 1;" ::: "memory")

__device__ __forceinline__ void ldm_x4(uint32_t* r, uint32_t addr) {
    asm volatile("ldmatrix.sync.aligned.m8n8.x4.shared.b16 {%0,%1,%2,%3}, [%4];"
                 : "=r"(r[0]), "=r"(r[1]), "=r"(r[2]), "=r"(r[3]) : "r"(addr));
}
__device__ __forceinline__ void ldm_x2(uint32_t* r, uint32_t addr) {
    asm volatile("ldmatrix.sync.aligned.m8n8.x2.shared.b16 {%0,%1}, [%2];"
                 : "=r"(r[0]), "=r"(r[1]) : "r"(addr));
}
__device__ __forceinline__ void ldm_x2_trans(uint32_t* r, uint32_t addr) {
    asm volatile("ldmatrix.sync.aligned.m8n8.x2.trans.shared.b16 {%0,%1}, [%2];"
                 : "=r"(r[0]), "=r"(r[1]) : "r"(addr));
}
// fp16 mma
__device__ __forceinline__ void mma16816h(float* c, const uint32_t* a, const uint32_t* b) {
    asm volatile("mma.sync.aligned.m16n8k16.row.col.f32.f16.f16.f32 "
                 "{%0,%1,%2,%3}, {%4,%5,%6,%7}, {%8,%9}, {%0,%1,%2,%3};"
                 : "+f"(c[0]), "+f"(c[1]), "+f"(c[2]), "+f"(c[3])
                 : "r"(a[0]), "r"(a[1]), "r"(a[2]), "r"(a[3]), "r"(b[0]), "r"(b[1]));
}
__device__ __forceinline__ uint32_t packh(float lo, float hi) {
    __half2 h = __floats2half2_rn(lo, hi);
    return *(uint32_t*)&h;
}

// ================= GEMM tiling constants =================
#define GT_ROWB   80
#define GT_TILE   (128 * GT_ROWB)          // 10240 B
#define G1_STAGE  (2 * GT_TILE)            // A, B = 20480 B
#define G1_NST    3
#define G1_TOTAL  (G1_NST * G1_STAGE)      // 61440 B -> 2 CTAs/SM

// Shared mainloop macro body: computes acc[4][4][4] for CTA tile (by,bx), K given.
#define GEMM_MAINLOOP(Ah, Bh, K)                                                   \
    const int r0c = tid >> 2,          c0c = tid & 3;                              \
    const int r1c = (tid + 256) >> 2;                                              \
    const size_t ga0 = (size_t)(by * 128 + r0c) * (K) + c0c * 8;                   \
    const size_t ga1 = (size_t)(by * 128 + r1c) * (K) + c0c * 8;                   \
    const size_t gb0 = (size_t)(bx * 128 + r0c) * (K) + c0c * 8;                   \
    const size_t gb1 = (size_t)(bx * 128 + r1c) * (K) + c0c * 8;                   \
    const uint32_t so0 = r0c * GT_ROWB + c0c * 16;                                 \
    const uint32_t so1 = r1c * GT_ROWB + c0c * 16;                                 \
    float acc[4][4][4];                                                            \
    _Pragma("unroll")                                                              \
    for (int i = 0; i < 4; i++)                                                    \
        _Pragma("unroll")                                                          \
        for (int j = 0; j < 4; j++)                                                \
            _Pragma("unroll")                                                      \
            for (int e = 0; e < 4; e++) acc[i][j][e] = 0.f;                        \
    const int n_kt = (K) >> 5;                                                     \
    const uint32_t a_row = (uint32_t)(m0 + (lane & 15));                           \
    const uint32_t a_coloff = (uint32_t)((lane >> 4) * 16);                        \
    const uint32_t b_row = (uint32_t)(n0 + (lane & 7));                            \
    const uint32_t b_coloff = (uint32_t)(((lane >> 3) & 1) * 16);                  \
    GLOAD(0, 0); GLOAD(1, 32);                                                     \
    int sidx = 0;                                                                  \
    for (int kt = 0; kt < n_kt; kt++) {                                            \
        if (kt + 1 < n_kt) { CP_WAIT1(); } else { CP_WAIT0(); }                    \
        __syncthreads();                                                           \
        if (kt + 2 < n_kt) {                                                       \
            int sn = sidx + 2; if (sn >= G1_NST) sn -= G1_NST;                     \
            GLOAD(sn, (size_t)(kt + 2) * 32);                                      \
        }                                                                          \
        const uint32_t st = sbase + sidx * G1_STAGE;                               \
        const uint32_t sA = st;                                                    \
        const uint32_t sB = st + GT_TILE;                                          \
        _Pragma("unroll")                                                          \
        for (int ks = 0; ks < 2; ks++) {                                           \
            const uint32_t kb = ks * 32;                                           \
            uint32_t af[4][4], bf[4][2];                                           \
            _Pragma("unroll")                                                      \
            for (int mt = 0; mt < 4; mt++)                                         \
                ldm_x4(af[mt], sA + (a_row + mt * 16) * GT_ROWB + kb + a_coloff);  \
            _Pragma("unroll")                                                      \
            for (int nt = 0; nt < 4; nt++)                                         \
                ldm_x2(bf[nt], sB + (b_row + nt * 8) * GT_ROWB + kb + b_coloff);   \
            _Pragma("unroll")                                                      \
            for (int mt = 0; mt < 4; mt++)                                         \
                _Pragma("unroll")                                                  \
                for (int nt = 0; nt < 4; nt++)                                     \
                    mma16816h(acc[mt][nt], af[mt], bf[nt]);                        \
        }                                                                          \
        sidx++; if (sidx >= G1_NST) sidx -= G1_NST;                                \
    }

#define GLOAD(sidx, ko)                                                    \
    do {                                                                   \
        const uint32_t st_ = sbase + (sidx) * G1_STAGE;                    \
        CP_ASYNC16(st_ + 0 * GT_TILE + so0, Ah + ga0 + (ko));              \
        CP_ASYNC16(st_ + 0 * GT_TILE + so1, Ah + ga1 + (ko));              \
        CP_ASYNC16(st_ + 1 * GT_TILE + so0, Bh + gb0 + (ko));              \
        CP_ASYNC16(st_ + 1 * GT_TILE + so1, Bh + gb1 + (ko));              \
        CP_COMMIT();                                                       \
    } while (0)

// ================= fused QKV GEMM: C = x @ Wqkv, epilogue does RoPE + fp16 =================
// bx in [0,16): q cols -> rope+scale -> g_qf ; [16,24): k cols -> rope -> g_kf ;
// [24,32): v cols -> g_vf.
__global__ __launch_bounds__(256, 2)
void gemm_qkv(const __half* __restrict__ Ah, const __half* __restrict__ Bh,
              const int* __restrict__ positions,
              __half* __restrict__ qf, __half* __restrict__ kf, __half* __restrict__ vf)
{
    extern __shared__ char smc[];
    const uint32_t sbase = smem_to_u32(smc);
    const int tid  = threadIdx.x;
    const int lane = tid & 31;
    const int wid  = tid >> 5;
    const int bx = blockIdx.x;
    const int by = blockIdx.y;
    const int m0 = (wid & 1) * 64;
    const int n0 = (wid >> 1) * 32;

    GEMM_MAINLOOP(Ah, Bh, DIM)

    const int g  = lane >> 2;
    const int tg = (lane & 3) * 2;
    const float scale = 0.08838834764831845f;
#pragma unroll
    for (int mt = 0; mt < 4; mt++) {
        const int r0 = by * 128 + m0 + mt * 16 + g;
        const int p0 = positions[r0];
        const int p1 = positions[r0 + 8];
#pragma unroll
        for (int nt = 0; nt < 4; nt++) {
            const int cc = bx * 128 + n0 + nt * 8 + tg;
            float v00 = acc[mt][nt][0], v01 = acc[mt][nt][1];
            float v10 = acc[mt][nt][2], v11 = acc[mt][nt][3];
            if (bx < 16) {
                const int pair = (cc & 127) >> 1;
                float2 c0 = g_rope[(p0 << 6) + pair];
                float2 c1 = g_rope[(p1 << 6) + pair];
                *(uint32_t*)(qf + (size_t)r0 * DIM + cc) =
                    packh((v00 * c0.x - v01 * c0.y) * scale,
                          (v00 * c0.y + v01 * c0.x) * scale);
                *(uint32_t*)(qf + (size_t)(r0 + 8) * DIM + cc) =
                    packh((v10 * c1.x - v11 * c1.y) * scale,
                          (v10 * c1.y + v11 * c1.x) * scale);
            } else if (bx < 24) {
                const int pair = (cc & 127) >> 1;
                float2 c0 = g_rope[(p0 << 6) + pair];
                float2 c1 = g_rope[(p1 << 6) + pair];
                const int c2 = cc - 2048;
                *(uint32_t*)(kf + (size_t)r0 * KV_DIM + c2) =
                    packh(v00 * c0.x - v01 * c0.y, v00 * c0.y + v01 * c0.x);
                *(uint32_t*)(kf + (size_t)(r0 + 8) * KV_DIM + c2) =
                    packh(v10 * c1.x - v11 * c1.y, v10 * c1.y + v11 * c1.x);
            } else {
                const int c2 = cc - 3072;
                *(uint32_t*)(vf + (size_t)r0 * KV_DIM + c2) = packh(v00, v01);
                *(uint32_t*)(vf + (size_t)(r0 + 8) * KV_DIM + c2) = packh(v10, v11);
            }
        }
    }
}

// ================= plain fp16 GEMM with fp32 output (wo) =================
__global__ __launch_bounds__(256, 2)
void gemm_h1(const __half* __restrict__ Ah, const __half* __restrict__ Bh,
             float* __restrict__ C, int Ncols, int K)
{
    extern __shared__ char smc[];
    const uint32_t sbase = smem_to_u32(smc);
    const int tid  = threadIdx.x;
    const int lane = tid & 31;
    const int wid  = tid >> 5;
    const int bx = blockIdx.x;
    const int by = blockIdx.y;
    const int m0 = (wid & 1) * 64;
    const int n0 = (wid >> 1) * 32;

    GEMM_MAINLOOP(Ah, Bh, K)

    const int g  = lane >> 2;
    const int tg = (lane & 3) * 2;
#pragma unroll
    for (int mt = 0; mt < 4; mt++) {
        const int r = by * 128 + m0 + mt * 16 + g;
#pragma unroll
        for (int nt = 0; nt < 4; nt++) {
            const int cc = bx * 128 + n0 + nt * 8 + tg;
            *(float2*)(C + (size_t)r * Ncols + cc) =
                make_float2(acc[mt][nt][0], acc[mt][nt][1]);
            *(float2*)(C + (size_t)(r + 8) * Ncols + cc) =
                make_float2(acc[mt][nt][2], acc[mt][nt][3]);
        }
    }
}

// ---------------- rope table: cos/sin per (pos, pair), computed in double ----------------
__global__ __launch_bounds__(256)
void rope_table()
{
    int idx = blockIdx.x * blockDim.x + threadIdx.x;
    if (idx >= S_LEN * 64) return;
    int pos = idx >> 6, pair = idx & 63;
    double inv = pow(10000.0, -(double)(2 * pair) / 128.0);
    double ang = (double)pos * inv;
    g_rope[idx] = make_float2((float)cos(ang), (float)sin(ang));
}

// ---------------- fp32 -> fp16 ----------------
__global__ __launch_bounds__(256)
void convert_h(const float* __restrict__ X, __half* __restrict__ H, int total)
{
    int i = blockIdx.x * blockDim.x + threadIdx.x;
    if (i >= total) return;
    H[i] = __float2half_rn(X[i]);
}

// ---------------- W[K,N] -> W^T fp16 [N,K] ----------------
__global__ __launch_bounds__(256)
void transpose_h(const float* __restrict__ W, __half* __restrict__ Th, int K, int N)
{
    __shared__ float t[32][33];
    int n0 = blockIdx.x * 32, k0 = blockIdx.y * 32;
    int tx = threadIdx.x & 31, ty = threadIdx.x >> 5;
#pragma unroll
    for (int j = 0; j < 4; j++)
        t[ty + j * 8][tx] = W[(size_t)(k0 + ty + j * 8) * N + n0 + tx];
    __syncthreads();
#pragma unroll
    for (int j = 0; j < 4; j++)
        Th[(size_t)(n0 + ty + j * 8) * K + k0 + tx] = __float2half_rn(t[tx][ty + j * 8]);
}

// ================= mma.sync flash attention (causal, GQA rep=2) =================
// Q single-pass fp16; P exact 2-pass; V single fp16.
#define AQ_ROWB 272
#define AQ_TILE (128 * AQ_ROWB)        // 34816
#define AKV_TILE (64 * AQ_ROWB)        // 17408
#define AKV_BUF (2 * AKV_TILE)         // 34816 (K + V)
#define AT_SMEM (AQ_TILE + 2 * AKV_BUF)   // 104448 B -> 1 CTA/SM (regs bound)

__global__ __launch_bounds__(256, 1)
void attn_mma(const __half* __restrict__ qf, const __half* __restrict__ kf,
              const __half* __restrict__ vf, __half* __restrict__ oh)
{
    extern __shared__ char smb[];
    const uint32_t sb  = smem_to_u32(smb);
    const uint32_t sQ  = sb;
    const uint32_t kv0 = sb + AQ_TILE;

    const int tid  = threadIdx.x;
    const int lane = tid & 31;
    const int wid  = tid >> 5;
    const int qt = blockIdx.x, h = blockIdx.y, b = blockIdx.z;
    const int kvh = h >> 1;
    const int q0 = qt * 128;
    const int m0 = wid * 16;
    const int g  = lane >> 2;
    const int tg = lane & 3;

    {
        const __half* srcQ = qf + (size_t)(b * S_LEN + q0) * DIM + h * HD;
        for (int c = tid; c < 2048; c += 256) {
            int r = c >> 4, cc = c & 15;
            CP_ASYNC16(sQ + r * AQ_ROWB + cc * 16, srcQ + (size_t)r * DIM + cc * 8);
        }
        CP_COMMIT();
    }

    const size_t kvbase0 = (size_t)(b * S_LEN) * KV_DIM + kvh * HD;

    {
        const __half* pK = kf + kvbase0;
        const __half* pV = vf + kvbase0;
        for (int c = tid; c < 1024; c += 256) {
            int r = c >> 4, cc = c & 15;
            uint32_t so = r * AQ_ROWB + cc * 16;
            size_t go = (size_t)r * KV_DIM + cc * 8;
            CP_ASYNC16(kv0 + 0 * AKV_TILE + so, pK + go);
            CP_ASYNC16(kv0 + 1 * AKV_TILE + so, pV + go);
        }
        CP_COMMIT();
    }

    float oacc[16][4];
#pragma unroll
    for (int nt = 0; nt < 16; nt++)
#pragma unroll
        for (int e = 0; e < 4; e++) oacc[nt][e] = 0.f;
    float mst0 = -1e30f, mst1 = -1e30f, lst0 = 0.f, lst1 = 0.f;

    const uint32_t qa_off = (uint32_t)((m0 + (lane & 15)) * AQ_ROWB + (lane >> 4) * 16);
    const uint32_t kb_row = (uint32_t)((lane & 7) * AQ_ROWB + ((lane >> 3) & 1) * 16);
    const uint32_t v_row  = (uint32_t)((lane & 15) * AQ_ROWB);

    const int ktmax = 2 * qt + 1;
    for (int kt = 0; kt <= ktmax; kt++) {
        const int cur = kt & 1;
        CP_WAIT0();
        __syncthreads();

        if (kt < ktmax) {
            const uint32_t kvn = kv0 + (cur ^ 1) * AKV_BUF;
            const size_t base = kvbase0 + (size_t)(kt + 1) * 64 * KV_DIM;
            const __half* pK = kf + base;
            const __half* pV = vf + base;
            for (int c = tid; c < 1024; c += 256) {
                int r = c >> 4, cc = c & 15;
                uint32_t so = r * AQ_ROWB + cc * 16;
                size_t go = (size_t)r * KV_DIM + cc * 8;
                CP_ASYNC16(kvn + 0 * AKV_TILE + so, pK + go);
                CP_ASYNC16(kvn + 1 * AKV_TILE + so, pV + go);
            }
            CP_COMMIT();
        }

        const uint32_t sK = kv0 + cur * AKV_BUF;
        const uint32_t sV = sK + AKV_TILE;

        // --- S = Q.K^T, single-pass fp16 ---
        float sacc[8][4];
#pragma unroll
        for (int j = 0; j < 8; j++)
#pragma unroll
            for (int e = 0; e < 4; e++) sacc[j][e] = 0.f;

#pragma unroll
        for (int kk = 0; kk < 8; kk++) {
            uint32_t qfr[4], kfr[2];
            ldm_x4(qfr, sQ + qa_off + kk * 32);
#pragma unroll
            for (int j = 0; j < 8; j++) {
                ldm_x2(kfr, sK + j * 8 * AQ_ROWB + kb_row + kk * 32);
                mma16816h(sacc[j], qfr, kfr);
            }
        }

        if (kt * 64 + 63 > q0 + m0 + g) {
            const int r0l = q0 + m0 + g, r1l = r0l + 8;
            const int cb = kt * 64 + tg * 2;
#pragma unroll
            for (int j = 0; j < 8; j++) {
                const int c0 = cb + j * 8;
                if (c0     > r0l) sacc[j][0] = -1e30f;
                if (c0 + 1 > r0l) sacc[j][1] = -1e30f;
                if (c0     > r1l) sacc[j][2] = -1e30f;
                if (c0 + 1 > r1l) sacc[j][3] = -1e30f;
            }
        }

        float mx0 = -1e30f, mx1 = -1e30f;
#pragma unroll
        for (int j = 0; j < 8; j++) {
            mx0 = fmaxf(mx0, fmaxf(sacc[j][0], sacc[j][1]));
            mx1 = fmaxf(mx1, fmaxf(sacc[j][2], sacc[j][3]));
        }
        mx0 = fmaxf(mx0, __shfl_xor_sync(0xffffffffu, mx0, 1));
        mx0 = fmaxf(mx0, __shfl_xor_sync(0xffffffffu, mx0, 2));
        mx1 = fmaxf(mx1, __shfl_xor_sync(0xffffffffu, mx1, 1));
        mx1 = fmaxf(mx1, __shfl_xor_sync(0xffffffffu, mx1, 2));
        const float nm0 = fmaxf(mst0, mx0);
        const float nm1 = fmaxf(mst1, mx1);
        const float a0 = expf(mst0 - nm0);
        const float a1 = expf(mst1 - nm1);
        mst0 = nm0; mst1 = nm1;
        float sum0 = 0.f, sum1 = 0.f;
#pragma unroll
        for (int j = 0; j < 8; j++) {
            sacc[j][0] = expf(sacc[j][0] - nm0);
            sacc[j][1] = expf(sacc[j][1] - nm0);
            sacc[j][2] = expf(sacc[j][2] - nm1);
            sacc[j][3] = expf(sacc[j][3] - nm1);
            sum0 += sacc[j][0] + sacc[j][1];
            sum1 += sacc[j][2] + sacc[j][3];
        }
        sum0 += __shfl_xor_sync(0xffffffffu, sum0, 1);
        sum0 += __shfl_xor_sync(0xffffffffu, sum0, 2);
        sum1 += __shfl_xor_sync(0xffffffffu, sum1, 1);
        sum1 += __shfl_xor_sync(0xffffffffu, sum1, 2);
        lst0 = lst0 * a0 + sum0;
        lst1 = lst1 * a1 + sum1;
#pragma unroll
        for (int nt = 0; nt < 16; nt++) {
            oacc[nt][0] *= a0; oacc[nt][1] *= a0;
            oacc[nt][2] *= a1; oacc[nt][3] *= a1;
        }

        // --- O += P.V  (P exact 2-pass, V rounded) ---
#pragma unroll
        for (int jk = 0; jk < 4; jk++) {
            uint32_t pfh[4], pfl[4];
#pragma unroll
            for (int q = 0; q < 2; q++) {
                const int j = 2 * jk + q;
#pragma unroll
                for (int pr = 0; pr < 2; pr++) {
                    float p0 = sacc[j][2 * pr], p1 = sacc[j][2 * pr + 1];
                    __half b0 = __float2half_rn(p0);
                    __half b1 = __float2half_rn(p1);
                    { __half2 t2 = __halves2half2(b0, b1); pfh[2 * q + pr] = *(uint32_t*)&t2; }
                    pfl[2 * q + pr] = packh(p0 - __half2float(b0),
                                            p1 - __half2float(b1));
                }
            }
            const uint32_t vbase = jk * 16 * AQ_ROWB + v_row;
#pragma unroll
            for (int nt = 0; nt < 16; nt++) {
                uint32_t vfr[2];
                ldm_x2_trans(vfr, sV + vbase + nt * 16);
                mma16816h(oacc[nt], pfh, vfr);
                mma16816h(oacc[nt], pfl, vfr);
            }
        }
    }

    // --- epilogue: normalize, store single fp16 ---
    const float inv0 = 1.f / lst0;
    const float inv1 = 1.f / lst1;
    const size_t r0g = (size_t)(b * S_LEN + q0 + m0 + g);
    const size_t r1g = r0g + 8;
    const int colb = h * HD + tg * 2;
#pragma unroll
    for (int nt = 0; nt < 16; nt++) {
        uint32_t hw0 = packh(oacc[nt][0] * inv0, oacc[nt][1] * inv0);
        uint32_t hw1 = packh(oacc[nt][2] * inv1, oacc[nt][3] * inv1);
        const int cc = colb + nt * 8;
        *(uint32_t*)(oh + r0g * DIM + cc) = hw0;
        *(uint32_t*)(oh + r1g * DIM + cc) = hw1;
    }
}

// ---------------- launcher ----------------
extern "C" void kernel_launch(void* const* d_in, const int* in_sizes, int n_in,
                              void* d_out, int out_size)
{
    const float* x  = (const float*)d_in[0];
    const float* wq = (const float*)d_in[1];
    const float* wk = (const float*)d_in[2];
    const float* wv = (const float*)d_in[3];
    const float* wo = (const float*)d_in[4];
    const int* positions = (const int*)d_in[7];
    float* out = (float*)d_out;

    __half *xf, *af, *wqkvT, *woT, *pqf, *pkf, *pvf;
    cudaGetSymbolAddress((void**)&xf, g_xf);
    cudaGetSymbolAddress((void**)&af, g_af);
    cudaGetSymbolAddress((void**)&wqkvT, g_wqkvT);
    cudaGetSymbolAddress((void**)&woT, g_woT);
    cudaGetSymbolAddress((void**)&pqf, g_qf);
    cudaGetSymbolAddress((void**)&pkf, g_kf);
    cudaGetSymbolAddress((void**)&pvf, g_vf);

    cudaFuncSetAttribute(gemm_qkv, cudaFuncAttributeMaxDynamicSharedMemorySize, G1_TOTAL);
    cudaFuncSetAttribute(gemm_h1,  cudaFuncAttributeMaxDynamicSharedMemorySize, G1_TOTAL);
    cudaFuncSetAttribute(attn_mma, cudaFuncAttributeMaxDynamicSharedMemorySize, AT_SMEM);

    // 1: rope table
    rope_table<<<(S_LEN * 64 + 255) / 256, 256>>>();
    // 2: x -> fp16
    {
        int total = T_TOK * DIM;
        convert_h<<<(total + 255) / 256, 256>>>(x, xf, total);
    }
    // 3-6: weight transposes
    transpose_h<<<dim3(DIM / 32,    DIM / 32), 256>>>(wq, wqkvT,              DIM, DIM);
    transpose_h<<<dim3(KV_DIM / 32, DIM / 32), 256>>>(wk, wqkvT + 2048 * DIM, DIM, KV_DIM);
    transpose_h<<<dim3(KV_DIM / 32, DIM / 32), 256>>>(wv, wqkvT + 3072 * DIM, DIM, KV_DIM);
    transpose_h<<<dim3(DIM / 32,    DIM / 32), 256>>>(wo, woT, DIM, DIM);
    // 7: fused QKV GEMM + RoPE + fp16 epilogue
    gemm_qkv<<<dim3(QKV_N / 128, T_TOK / 128), 256, G1_TOTAL>>>(xf, wqkvT, positions,
                                                                pqf, pkf, pvf);
    // 8: flash attention
    attn_mma<<<dim3(S_LEN / 128, NH, B_SZ), 256, AT_SMEM>>>(pqf, pkf, pvf, af);
    // 9: output projection
    gemm_h1<<<dim3(DIM / 128, T_TOK / 128), 256, G1_TOTAL>>>(af, woT, out, DIM, DIM);
}

// round 14
// speedup vs baseline: 4.8353x; 1.0418x over previous
#include <cuda_runtime.h>
#include <cuda_bf16.h>
#include <cuda_fp16.h>
#include <cstdint>
#include <math.h>

// ---------------- problem constants ----------------
#define T_TOK   8192
#define DIM     2048
#define NH      16
#define NKV     8
#define HD      128
#define S_LEN   1024
#define B_SZ    8
#define KV_DIM  1024      // NKV * HD
#define QKV_N   4096      // DIM + 2*KV_DIM

// ---------------- scratch ----------------
__device__ float2 g_rope[S_LEN * 64];      // cos/sin per (pos, pair)

// fp16 activations
__device__ __half g_xf[T_TOK * DIM];       // x single fp16 (QKV gemm A)
__device__ __half g_af[T_TOK * DIM];       // attn out single fp16 (wo gemm A)
// fp16 transposed weights [N,K]
__device__ __half g_wqkvT[QKV_N * DIM];    // rows: 0-2047 wq^T, 2048-3071 wk^T, 3072-4095 wv^T
__device__ __half g_woT[DIM * DIM];
// fp16 attention operands (written by fused QKV gemm epilogue)
__device__ __half g_qf[T_TOK * DIM];       // q (roped, scaled) fp16
__device__ __half g_kf[T_TOK * KV_DIM];    // k (roped) fp16
__device__ __half g_vf[T_TOK * KV_DIM];    // v fp16

// ================= low-level helpers (sm_80-class PTX only) =================
__device__ __forceinline__ uint32_t smem_to_u32(const void* smem_ptr) {
    uint32_t addr;
    asm("{ .reg .u64 tmp; cvta.to.shared.u64 tmp, %1; cvt.u32.u64 %0, tmp; }"
        : "=r"(addr) : "l"(smem_ptr));
    return addr;
}

#define CP_ASYNC16(dst_u32, src_ptr) \
    asm volatile("cp.async.cg.shared.global [%0], [%1], 16;" \
                 :: "r"(dst_u32), "l"(src_ptr) : "memory")
#define CP_COMMIT() asm volatile("cp.async.commit_group;" ::: "memory")
#define CP_WAIT0()  asm volatile("cp.async.wait_group 0;" ::: "memory")
#define CP_WAIT1()  asm volatile("cp.async.wait_group 1;" ::: "memory")

__device__ __forceinline__ void ldm_x4(uint32_t* r, uint32_t addr) {
    asm volatile("ldmatrix.sync.aligned.m8n8.x4.shared.b16 {%0,%1,%2,%3}, [%4];"
                 : "=r"(r[0]), "=r"(r[1]), "=r"(r[2]), "=r"(r[3]) : "r"(addr));
}
__device__ __forceinline__ void ldm_x2(uint32_t* r, uint32_t addr) {
    asm volatile("ldmatrix.sync.aligned.m8n8.x2.shared.b16 {%0,%1}, [%2];"
                 : "=r"(r[0]), "=r"(r[1]) : "r"(addr));
}
__device__ __forceinline__ void ldm_x2_trans(uint32_t* r, uint32_t addr) {
    asm volatile("ldmatrix.sync.aligned.m8n8.x2.trans.shared.b16 {%0,%1}, [%2];"
                 : "=r"(r[0]), "=r"(r[1]) : "r"(addr));
}
// fp16 mma
__device__ __forceinline__ void mma16816h(float* c, const uint32_t* a, const uint32_t* b) {
    asm volatile("mma.sync.aligned.m16n8k16.row.col.f32.f16.f16.f32 "
                 "{%0,%1,%2,%3}, {%4,%5,%6,%7}, {%8,%9}, {%0,%1,%2,%3};"
                 : "+f"(c[0]), "+f"(c[1]), "+f"(c[2]), "+f"(c[3])
                 : "r"(a[0]), "r"(a[1]), "r"(a[2]), "r"(a[3]), "r"(b[0]), "r"(b[1]));
}
__device__ __forceinline__ uint32_t packh(float lo, float hi) {
    __half2 h = __floats2half2_rn(lo, hi);
    return *(uint32_t*)&h;
}

// ================= GEMM tiling constants =================
#define GT_ROWB   80
#define GT_TILE   (128 * GT_ROWB)          // 10240 B
#define G1_STAGE  (2 * GT_TILE)            // A, B = 20480 B
#define G1_NST    3
#define G1_TOTAL  (G1_NST * G1_STAGE)      // 61440 B -> 2 CTAs/SM

// Shared mainloop macro body: computes acc[4][4][4] for CTA tile (by,bx), K given.
#define GEMM_MAINLOOP(Ah, Bh, K)                                                   \
    const int r0c = tid >> 2,          c0c = tid & 3;                              \
    const int r1c = (tid + 256) >> 2;                                              \
    const size_t ga0 = (size_t)(by * 128 + r0c) * (K) + c0c * 8;                   \
    const size_t ga1 = (size_t)(by * 128 + r1c) * (K) + c0c * 8;                   \
    const size_t gb0 = (size_t)(bx * 128 + r0c) * (K) + c0c * 8;                   \
    const size_t gb1 = (size_t)(bx * 128 + r1c) * (K) + c0c * 8;                   \
    const uint32_t so0 = r0c * GT_ROWB + c0c * 16;                                 \
    const uint32_t so1 = r1c * GT_ROWB + c0c * 16;                                 \
    float acc[4][4][4];                                                            \
    _Pragma("unroll")                                                              \
    for (int i = 0; i < 4; i++)                                                    \
        _Pragma("unroll")                                                          \
        for (int j = 0; j < 4; j++)                                                \
            _Pragma("unroll")                                                      \
            for (int e = 0; e < 4; e++) acc[i][j][e] = 0.f;                        \
    const int n_kt = (K) >> 5;                                                     \
    const uint32_t a_row = (uint32_t)(m0 + (lane & 15));                           \
    const uint32_t a_coloff = (uint32_t)((lane >> 4) * 16);                        \
    const uint32_t b_row = (uint32_t)(n0 + (lane & 7));                            \
    const uint32_t b_coloff = (uint32_t)(((lane >> 3) & 1) * 16);                  \
    GLOAD(0, 0); GLOAD(1, 32);                                                     \
    int sidx = 0;                                                                  \
    for (int kt = 0; kt < n_kt; kt++) {                                            \
        if (kt + 1 < n_kt) { CP_WAIT1(); } else { CP_WAIT0(); }                    \
        __syncthreads();                                                           \
        if (kt + 2 < n_kt) {                                                       \
            int sn = sidx + 2; if (sn >= G1_NST) sn -= G1_NST;                     \
            GLOAD(sn, (size_t)(kt + 2) * 32);                                      \
        }                                                                          \
        const uint32_t st = sbase + sidx * G1_STAGE;                               \
        const uint32_t sA = st;                                                    \
        const uint32_t sB = st + GT_TILE;                                          \
        _Pragma("unroll")                                                          \
        for (int ks = 0; ks < 2; ks++) {                                           \
            const uint32_t kb = ks * 32;                                           \
            uint32_t af[4][4], bf[4][2];                                           \
            _Pragma("unroll")                                                      \
            for (int mt = 0; mt < 4; mt++)                                         \
                ldm_x4(af[mt], sA + (a_row + mt * 16) * GT_ROWB + kb + a_coloff);  \
            _Pragma("unroll")                                                      \
            for (int nt = 0; nt < 4; nt++)                                         \
                ldm_x2(bf[nt], sB + (b_row + nt * 8) * GT_ROWB + kb + b_coloff);   \
            _Pragma("unroll")                                                      \
            for (int mt = 0; mt < 4; mt++)                                         \
                _Pragma("unroll")                                                  \
                for (int nt = 0; nt < 4; nt++)                                     \
                    mma16816h(acc[mt][nt], af[mt], bf[nt]);                        \
        }                                                                          \
        sidx++; if (sidx >= G1_NST) sidx -= G1_NST;                                \
    }

#define GLOAD(sidx, ko)                                                    \
    do {                                                                   \
        const uint32_t st_ = sbase + (sidx) * G1_STAGE;                    \
        CP_ASYNC16(st_ + 0 * GT_TILE + so0, Ah + ga0 + (ko));              \
        CP_ASYNC16(st_ + 0 * GT_TILE + so1, Ah + ga1 + (ko));              \
        CP_ASYNC16(st_ + 1 * GT_TILE + so0, Bh + gb0 + (ko));              \
        CP_ASYNC16(st_ + 1 * GT_TILE + so1, Bh + gb1 + (ko));              \
        CP_COMMIT();                                                       \
    } while (0)

// ================= fused QKV GEMM: C = x @ Wqkv, epilogue does RoPE + fp16 =================
__global__ __launch_bounds__(256, 2)
void gemm_qkv(const __half* __restrict__ Ah, const __half* __restrict__ Bh,
              const int* __restrict__ positions,
              __half* __restrict__ qf, __half* __restrict__ kf, __half* __restrict__ vf)
{
    extern __shared__ char smc[];
    const uint32_t sbase = smem_to_u32(smc);
    const int tid  = threadIdx.x;
    const int lane = tid & 31;
    const int wid  = tid >> 5;
    const int bx = blockIdx.x;
    const int by = blockIdx.y;
    const int m0 = (wid & 1) * 64;
    const int n0 = (wid >> 1) * 32;

    GEMM_MAINLOOP(Ah, Bh, DIM)

    const int g  = lane >> 2;
    const int tg = (lane & 3) * 2;
    const float scale = 0.08838834764831845f;
#pragma unroll
    for (int mt = 0; mt < 4; mt++) {
        const int r0 = by * 128 + m0 + mt * 16 + g;
        const int p0 = positions[r0];
        const int p1 = positions[r0 + 8];
#pragma unroll
        for (int nt = 0; nt < 4; nt++) {
            const int cc = bx * 128 + n0 + nt * 8 + tg;
            float v00 = acc[mt][nt][0], v01 = acc[mt][nt][1];
            float v10 = acc[mt][nt][2], v11 = acc[mt][nt][3];
            if (bx < 16) {
                const int pair = (cc & 127) >> 1;
                float2 c0 = g_rope[(p0 << 6) + pair];
                float2 c1 = g_rope[(p1 << 6) + pair];
                *(uint32_t*)(qf + (size_t)r0 * DIM + cc) =
                    packh((v00 * c0.x - v01 * c0.y) * scale,
                          (v00 * c0.y + v01 * c0.x) * scale);
                *(uint32_t*)(qf + (size_t)(r0 + 8) * DIM + cc) =
                    packh((v10 * c1.x - v11 * c1.y) * scale,
                          (v10 * c1.y + v11 * c1.x) * scale);
            } else if (bx < 24) {
                const int pair = (cc & 127) >> 1;
                float2 c0 = g_rope[(p0 << 6) + pair];
                float2 c1 = g_rope[(p1 << 6) + pair];
                const int c2 = cc - 2048;
                *(uint32_t*)(kf + (size_t)r0 * KV_DIM + c2) =
                    packh(v00 * c0.x - v01 * c0.y, v00 * c0.y + v01 * c0.x);
                *(uint32_t*)(kf + (size_t)(r0 + 8) * KV_DIM + c2) =
                    packh(v10 * c1.x - v11 * c1.y, v10 * c1.y + v11 * c1.x);
            } else {
                const int c2 = cc - 3072;
                *(uint32_t*)(vf + (size_t)r0 * KV_DIM + c2) = packh(v00, v01);
                *(uint32_t*)(vf + (size_t)(r0 + 8) * KV_DIM + c2) = packh(v10, v11);
            }
        }
    }
}

// ================= plain fp16 GEMM with fp32 output (wo) =================
__global__ __launch_bounds__(256, 2)
void gemm_h1(const __half* __restrict__ Ah, const __half* __restrict__ Bh,
             float* __restrict__ C, int Ncols, int K)
{
    extern __shared__ char smc[];
    const uint32_t sbase = smem_to_u32(smc);
    const int tid  = threadIdx.x;
    const int lane = tid & 31;
    const int wid  = tid >> 5;
    const int bx = blockIdx.x;
    const int by = blockIdx.y;
    const int m0 = (wid & 1) * 64;
    const int n0 = (wid >> 1) * 32;

    GEMM_MAINLOOP(Ah, Bh, K)

    const int g  = lane >> 2;
    const int tg = (lane & 3) * 2;
#pragma unroll
    for (int mt = 0; mt < 4; mt++) {
        const int r = by * 128 + m0 + mt * 16 + g;
#pragma unroll
        for (int nt = 0; nt < 4; nt++) {
            const int cc = bx * 128 + n0 + nt * 8 + tg;
            *(float2*)(C + (size_t)r * Ncols + cc) =
                make_float2(acc[mt][nt][0], acc[mt][nt][1]);
            *(float2*)(C + (size_t)(r + 8) * Ncols + cc) =
                make_float2(acc[mt][nt][2], acc[mt][nt][3]);
        }
    }
}

// ---------------- rope table: cos/sin per (pos, pair), computed in double ----------------
__global__ __launch_bounds__(256)
void rope_table()
{
    int idx = blockIdx.x * blockDim.x + threadIdx.x;
    if (idx >= S_LEN * 64) return;
    int pos = idx >> 6, pair = idx & 63;
    double inv = pow(10000.0, -(double)(2 * pair) / 128.0);
    double ang = (double)pos * inv;
    g_rope[idx] = make_float2((float)cos(ang), (float)sin(ang));
}

// ---------------- fp32 -> fp16 ----------------
__global__ __launch_bounds__(256)
void convert_h(const float* __restrict__ X, __half* __restrict__ H, int total)
{
    int i = blockIdx.x * blockDim.x + threadIdx.x;
    if (i >= total) return;
    H[i] = __float2half_rn(X[i]);
}

// ---------------- all 4 weight transposes in one launch ----------------
// sources all [2048, N]; z selects weight
__global__ __launch_bounds__(256)
void transpose_all(const float* __restrict__ wq, const float* __restrict__ wk,
                   const float* __restrict__ wv, const float* __restrict__ wo,
                   __half* __restrict__ wqkvT, __half* __restrict__ woT)
{
    const int z = blockIdx.z;
    const float* W;
    __half* Th;
    int N;
    if (z == 0)      { W = wq; Th = wqkvT;              N = 2048; }
    else if (z == 1) { W = wk; Th = wqkvT + 2048 * DIM; N = 1024; }
    else if (z == 2) { W = wv; Th = wqkvT + 3072 * DIM; N = 1024; }
    else             { W = wo; Th = woT;                N = 2048; }

    int n0 = blockIdx.x * 32;
    if (n0 >= N) return;
    int k0 = blockIdx.y * 32;

    __shared__ float t[32][33];
    int tx = threadIdx.x & 31, ty = threadIdx.x >> 5;
#pragma unroll
    for (int j = 0; j < 4; j++)
        t[ty + j * 8][tx] = W[(size_t)(k0 + ty + j * 8) * N + n0 + tx];
    __syncthreads();
#pragma unroll
    for (int j = 0; j < 4; j++)
        Th[(size_t)(n0 + ty + j * 8) * DIM + k0 + tx] = __float2half_rn(t[tx][ty + j * 8]);
}

// ================= mma.sync flash attention (causal, GQA rep=2) =================
// Q, K, V, P all single fp16 (error budget per calibrated model).
#define AQ_ROWB 272
#define AQ_TILE (128 * AQ_ROWB)        // 34816
#define AKV_TILE (64 * AQ_ROWB)        // 17408
#define AKV_BUF (2 * AKV_TILE)         // 34816 (K + V)
#define AT_SMEM (AQ_TILE + 2 * AKV_BUF)   // 104448 B

__global__ __launch_bounds__(256, 1)
void attn_mma(const __half* __restrict__ qf, const __half* __restrict__ kf,
              const __half* __restrict__ vf, __half* __restrict__ oh)
{
    extern __shared__ char smb[];
    const uint32_t sb  = smem_to_u32(smb);
    const uint32_t sQ  = sb;
    const uint32_t kv0 = sb + AQ_TILE;

    const int tid  = threadIdx.x;
    const int lane = tid & 31;
    const int wid  = tid >> 5;
    const int qt = blockIdx.x, h = blockIdx.y, b = blockIdx.z;
    const int kvh = h >> 1;
    const int q0 = qt * 128;
    const int m0 = wid * 16;
    const int g  = lane >> 2;
    const int tg = lane & 3;

    {
        const __half* srcQ = qf + (size_t)(b * S_LEN + q0) * DIM + h * HD;
        for (int c = tid; c < 2048; c += 256) {
            int r = c >> 4, cc = c & 15;
            CP_ASYNC16(sQ + r * AQ_ROWB + cc * 16, srcQ + (size_t)r * DIM + cc * 8);
        }
        CP_COMMIT();
    }

    const size_t kvbase0 = (size_t)(b * S_LEN) * KV_DIM + kvh * HD;

    {
        const __half* pK = kf + kvbase0;
        const __half* pV = vf + kvbase0;
        for (int c = tid; c < 1024; c += 256) {
            int r = c >> 4, cc = c & 15;
            uint32_t so = r * AQ_ROWB + cc * 16;
            size_t go = (size_t)r * KV_DIM + cc * 8;
            CP_ASYNC16(kv0 + 0 * AKV_TILE + so, pK + go);
            CP_ASYNC16(kv0 + 1 * AKV_TILE + so, pV + go);
        }
        CP_COMMIT();
    }

    float oacc[16][4];
#pragma unroll
    for (int nt = 0; nt < 16; nt++)
#pragma unroll
        for (int e = 0; e < 4; e++) oacc[nt][e] = 0.f;
    float mst0 = -1e30f, mst1 = -1e30f, lst0 = 0.f, lst1 = 0.f;

    const uint32_t qa_off = (uint32_t)((m0 + (lane & 15)) * AQ_ROWB + (lane >> 4) * 16);
    const uint32_t kb_row = (uint32_t)((lane & 7) * AQ_ROWB + ((lane >> 3) & 1) * 16);
    const uint32_t v_row  = (uint32_t)((lane & 15) * AQ_ROWB);

    const int ktmax = 2 * qt + 1;
    for (int kt = 0; kt <= ktmax; kt++) {
        const int cur = kt & 1;
        CP_WAIT0();
        __syncthreads();

        if (kt < ktmax) {
            const uint32_t kvn = kv0 + (cur ^ 1) * AKV_BUF;
            const size_t base = kvbase0 + (size_t)(kt + 1) * 64 * KV_DIM;
            const __half* pK = kf + base;
            const __half* pV = vf + base;
            for (int c = tid; c < 1024; c += 256) {
                int r = c >> 4, cc = c & 15;
                uint32_t so = r * AQ_ROWB + cc * 16;
                size_t go = (size_t)r * KV_DIM + cc * 8;
                CP_ASYNC16(kvn + 0 * AKV_TILE + so, pK + go);
                CP_ASYNC16(kvn + 1 * AKV_TILE + so, pV + go);
            }
            CP_COMMIT();
        }

        const uint32_t sK = kv0 + cur * AKV_BUF;
        const uint32_t sV = sK + AKV_TILE;

        // --- S = Q.K^T, single-pass fp16 ---
        float sacc[8][4];
#pragma unroll
        for (int j = 0; j < 8; j++)
#pragma unroll
            for (int e = 0; e < 4; e++) sacc[j][e] = 0.f;

#pragma unroll
        for (int kk = 0; kk < 8; kk++) {
            uint32_t qfr[4], kfr[2];
            ldm_x4(qfr, sQ + qa_off + kk * 32);
#pragma unroll
            for (int j = 0; j < 8; j++) {
                ldm_x2(kfr, sK + j * 8 * AQ_ROWB + kb_row + kk * 32);
                mma16816h(sacc[j], qfr, kfr);
            }
        }

        if (kt * 64 + 63 > q0 + m0 + g) {
            const int r0l = q0 + m0 + g, r1l = r0l + 8;
            const int cb = kt * 64 + tg * 2;
#pragma unroll
            for (int j = 0; j < 8; j++) {
                const int c0 = cb + j * 8;
                if (c0     > r0l) sacc[j][0] = -1e30f;
                if (c0 + 1 > r0l) sacc[j][1] = -1e30f;
                if (c0     > r1l) sacc[j][2] = -1e30f;
                if (c0 + 1 > r1l) sacc[j][3] = -1e30f;
            }
        }

        float mx0 = -1e30f, mx1 = -1e30f;
#pragma unroll
        for (int j = 0; j < 8; j++) {
            mx0 = fmaxf(mx0, fmaxf(sacc[j][0], sacc[j][1]));
            mx1 = fmaxf(mx1, fmaxf(sacc[j][2], sacc[j][3]));
        }
        mx0 = fmaxf(mx0, __shfl_xor_sync(0xffffffffu, mx0, 1));
        mx0 = fmaxf(mx0, __shfl_xor_sync(0xffffffffu, mx0, 2));
        mx1 = fmaxf(mx1, __shfl_xor_sync(0xffffffffu, mx1, 1));
        mx1 = fmaxf(mx1, __shfl_xor_sync(0xffffffffu, mx1, 2));
        const float nm0 = fmaxf(mst0, mx0);
        const float nm1 = fmaxf(mst1, mx1);
        const float a0 = expf(mst0 - nm0);
        const float a1 = expf(mst1 - nm1);
        mst0 = nm0; mst1 = nm1;
        float sum0 = 0.f, sum1 = 0.f;
#pragma unroll
        for (int j = 0; j < 8; j++) {
            sacc[j][0] = expf(sacc[j][0] - nm0);
            sacc[j][1] = expf(sacc[j][1] - nm0);
            sacc[j][2] = expf(sacc[j][2] - nm1);
            sacc[j][3] = expf(sacc[j][3] - nm1);
            sum0 += sacc[j][0] + sacc[j][1];
            sum1 += sacc[j][2] + sacc[j][3];
        }
        sum0 += __shfl_xor_sync(0xffffffffu, sum0, 1);
        sum0 += __shfl_xor_sync(0xffffffffu, sum0, 2);
        sum1 += __shfl_xor_sync(0xffffffffu, sum1, 1);
        sum1 += __shfl_xor_sync(0xffffffffu, sum1, 2);
        lst0 = lst0 * a0 + sum0;
        lst1 = lst1 * a1 + sum1;
#pragma unroll
        for (int nt = 0; nt < 16; nt++) {
            oacc[nt][0] *= a0; oacc[nt][1] *= a0;
            oacc[nt][2] *= a1; oacc[nt][3] *= a1;
        }

        // --- O += P.V  (P single fp16, V fp16) ---
#pragma unroll
        for (int jk = 0; jk < 4; jk++) {
            uint32_t pf[4];
#pragma unroll
            for (int q = 0; q < 2; q++) {
                const int j = 2 * jk + q;
                pf[2 * q + 0] = packh(sacc[j][0], sacc[j][1]);
                pf[2 * q + 1] = packh(sacc[j][2], sacc[j][3]);
            }
            const uint32_t vbase = jk * 16 * AQ_ROWB + v_row;
#pragma unroll
            for (int nt = 0; nt < 16; nt++) {
                uint32_t vfr[2];
                ldm_x2_trans(vfr, sV + vbase + nt * 16);
                mma16816h(oacc[nt], pf, vfr);
            }
        }
    }

    // --- epilogue: normalize, store single fp16 ---
    const float inv0 = 1.f / lst0;
    const float inv1 = 1.f / lst1;
    const size_t r0g = (size_t)(b * S_LEN + q0 + m0 + g);
    const size_t r1g = r0g + 8;
    const int colb = h * HD + tg * 2;
#pragma unroll
    for (int nt = 0; nt < 16; nt++) {
        uint32_t hw0 = packh(oacc[nt][0] * inv0, oacc[nt][1] * inv0);
        uint32_t hw1 = packh(oacc[nt][2] * inv1, oacc[nt][3] * inv1);
        const int cc = colb + nt * 8;
        *(uint32_t*)(oh + r0g * DIM + cc) = hw0;
        *(uint32_t*)(oh + r1g * DIM + cc) = hw1;
    }
}

// ---------------- launcher ----------------
extern "C" void kernel_launch(void* const* d_in, const int* in_sizes, int n_in,
                              void* d_out, int out_size)
{
    const float* x  = (const float*)d_in[0];
    const float* wq = (const float*)d_in[1];
    const float* wk = (const float*)d_in[2];
    const float* wv = (const float*)d_in[3];
    const float* wo = (const float*)d_in[4];
    const int* positions = (const int*)d_in[7];
    float* out = (float*)d_out;

    __half *xf, *af, *wqkvT, *woT, *pqf, *pkf, *pvf;
    cudaGetSymbolAddress((void**)&xf, g_xf);
    cudaGetSymbolAddress((void**)&af, g_af);
    cudaGetSymbolAddress((void**)&wqkvT, g_wqkvT);
    cudaGetSymbolAddress((void**)&woT, g_woT);
    cudaGetSymbolAddress((void**)&pqf, g_qf);
    cudaGetSymbolAddress((void**)&pkf, g_kf);
    cudaGetSymbolAddress((void**)&pvf, g_vf);

    cudaFuncSetAttribute(gemm_qkv, cudaFuncAttributeMaxDynamicSharedMemorySize, G1_TOTAL);
    cudaFuncSetAttribute(gemm_h1,  cudaFuncAttributeMaxDynamicSharedMemorySize, G1_TOTAL);
    cudaFuncSetAttribute(attn_mma, cudaFuncAttributeMaxDynamicSharedMemorySize, AT_SMEM);

    // 1: rope table
    rope_table<<<(S_LEN * 64 + 255) / 256, 256>>>();
    // 2: x -> fp16
    {
        int total = T_TOK * DIM;
        convert_h<<<(total + 255) / 256, 256>>>(x, xf, total);
    }
    // 3: all weight transposes in one launch
    transpose_all<<<dim3(64, 64, 4), 256>>>(wq, wk, wv, wo, wqkvT, woT);
    // 4: fused QKV GEMM + RoPE + fp16 epilogue
    gemm_qkv<<<dim3(QKV_N / 128, T_TOK / 128), 256, G1_TOTAL>>>(xf, wqkvT, positions,
                                                                pqf, pkf, pvf);
    // 5: flash attention
    attn_mma<<<dim3(S_LEN / 128, NH, B_SZ), 256, AT_SMEM>>>(pqf, pkf, pvf, af);
    // 6: output projection
    gemm_h1<<<dim3(DIM / 128, T_TOK / 128), 256, G1_TOTAL>>>(af, woT, out, DIM, DIM);
}

// round 16
// speedup vs baseline: 5.5158x; 1.1407x over previous
#include <cuda_runtime.h>
#include <cuda_bf16.h>
#include <cuda_fp16.h>
#include <cstdint>
#include <math.h>

// ---------------- problem constants ----------------
#define T_TOK   8192
#define DIM     2048
#define NH      16
#define NKV     8
#define HD      128
#define S_LEN   1024
#define B_SZ    8
#define KV_DIM  1024      // NKV * HD
#define QKV_N   4096      // DIM + 2*KV_DIM

// ---------------- scratch ----------------
__device__ float2 g_rope[S_LEN * 64];      // cos/sin per (pos, pair)

// fp16 activations
__device__ __half g_xf[T_TOK * DIM];       // x single fp16 (QKV gemm A)
__device__ __half g_af[T_TOK * DIM];       // attn out single fp16 (wo gemm A)
// fp16 transposed weights [N,K]
__device__ __half g_wqkvT[QKV_N * DIM];    // rows: 0-2047 wq^T, 2048-3071 wk^T, 3072-4095 wv^T
__device__ __half g_woT[DIM * DIM];
// fp16 attention operands (written by fused QKV gemm epilogue)
__device__ __half g_qf[T_TOK * DIM];       // q (roped, scaled) fp16
__device__ __half g_kf[T_TOK * KV_DIM];    // k (roped) fp16
__device__ __half g_vf[T_TOK * KV_DIM];    // v fp16

// ================= low-level helpers (sm_80-class PTX only) =================
__device__ __forceinline__ uint32_t smem_to_u32(const void* smem_ptr) {
    uint32_t addr;
    asm("{ .reg .u64 tmp; cvta.to.shared.u64 tmp, %1; cvt.u32.u64 %0, tmp; }"
        : "=r"(addr) : "l"(smem_ptr));
    return addr;
}

#define CP_ASYNC16(dst_u32, src_ptr) \
    asm volatile("cp.async.cg.shared.global [%0], [%1], 16;" \
                 :: "r"(dst_u32), "l"(src_ptr) : "memory")
#define CP_COMMIT() asm volatile("cp.async.commit_group;" ::: "memory")
#define CP_WAIT0()  asm volatile("cp.async.wait_group 0;" ::: "memory")
#define CP_WAIT1()  asm volatile("cp.async.wait_group 1;" ::: "memory")

__device__ __forceinline__ void ldm_x4(uint32_t* r, uint32_t addr) {
    asm volatile("ldmatrix.sync.aligned.m8n8.x4.shared.b16 {%0,%1,%2,%3}, [%4];"
                 : "=r"(r[0]), "=r"(r[1]), "=r"(r[2]), "=r"(r[3]) : "r"(addr));
}
__device__ __forceinline__ void ldm_x2_trans(uint32_t* r, uint32_t addr) {
    asm volatile("ldmatrix.sync.aligned.m8n8.x2.trans.shared.b16 {%0,%1}, [%2];"
                 : "=r"(r[0]), "=r"(r[1]) : "r"(addr));
}
__device__ __forceinline__ void ldm_x2(uint32_t* r, uint32_t addr) {
    asm volatile("ldmatrix.sync.aligned.m8n8.x2.shared.b16 {%0,%1}, [%2];"
                 : "=r"(r[0]), "=r"(r[1]) : "r"(addr));
}
// fp16 mma
__device__ __forceinline__ void mma16816h(float* c, const uint32_t* a, const uint32_t* b) {
    asm volatile("mma.sync.aligned.m16n8k16.row.col.f32.f16.f16.f32 "
                 "{%0,%1,%2,%3}, {%4,%5,%6,%7}, {%8,%9}, {%0,%1,%2,%3};"
                 : "+f"(c[0]), "+f"(c[1]), "+f"(c[2]), "+f"(c[3])
                 : "r"(a[0]), "r"(a[1]), "r"(a[2]), "r"(a[3]), "r"(b[0]), "r"(b[1]));
}
__device__ __forceinline__ uint32_t packh(float lo, float hi) {
    __half2 h = __floats2half2_rn(lo, hi);
    return *(uint32_t*)&h;
}

// ================= GEMM tiling: CTA 128x128, K-tile 64, 3-stage =================
// Row = 64 fp16 = 128 B data + 16 B pad = 144 B (16B-aligned chunks; ldmatrix
// row stride = 36 words = 4 banks -> 8 consecutive rows hit 8 distinct bank-quads).
#define GB_ROWB   144
#define GB_TILE   (128 * GB_ROWB)          // 18432 B
#define GB_STAGE  (2 * GB_TILE)            // A + B = 36864 B
#define GB_NST    3
#define GB_TOTAL  (GB_NST * GB_STAGE)      // 110592 B -> 2 CTAs/SM (221184 < 228KB)

// 8 cp.async per thread per stage (4 A rows-chunks + 4 B), K fixed at 2048.
#define GLOAD64(sidx, ko)                                                        \
    do {                                                                         \
        const uint32_t st_ = sbase + (sidx) * GB_STAGE;                          \
        CP_ASYNC16(st_ + so0 +  0 * 4608, Ah + ga0 +  0 * 65536 + (ko));         \
        CP_ASYNC16(st_ + so0 +  1 * 4608, Ah + ga0 +  1 * 65536 + (ko));         \
        CP_ASYNC16(st_ + so0 +  2 * 4608, Ah + ga0 +  2 * 65536 + (ko));         \
        CP_ASYNC16(st_ + so0 +  3 * 4608, Ah + ga0 +  3 * 65536 + (ko));         \
        CP_ASYNC16(st_ + GB_TILE + so0 + 0 * 4608, Bh + gb0 + 0 * 65536 + (ko)); \
        CP_ASYNC16(st_ + GB_TILE + so0 + 1 * 4608, Bh + gb0 + 1 * 65536 + (ko)); \
        CP_ASYNC16(st_ + GB_TILE + so0 + 2 * 4608, Bh + gb0 + 2 * 65536 + (ko)); \
        CP_ASYNC16(st_ + GB_TILE + so0 + 3 * 4608, Bh + gb0 + 3 * 65536 + (ko)); \
        CP_COMMIT();                                                             \
    } while (0)

// mainloop: K = 2048 fixed, 32 K-tiles of 64; single barrier per tile.
#define GEMM_MAINLOOP64(Ah, Bh)                                                  \
    const int c8  = tid & 7;                                                     \
    const int r0c = tid >> 3;                                                    \
    const size_t ga0 = (size_t)(by * 128 + r0c) * 2048 + c8 * 8;                 \
    const size_t gb0 = (size_t)(bx * 128 + r0c) * 2048 + c8 * 8;                 \
    const uint32_t so0 = r0c * GB_ROWB + c8 * 16;                                \
    float acc[4][4][4];                                                          \
    _Pragma("unroll")                                                            \
    for (int i = 0; i < 4; i++)                                                  \
        _Pragma("unroll")                                                        \
        for (int j = 0; j < 4; j++)                                              \
            _Pragma("unroll")                                                    \
            for (int e = 0; e < 4; e++) acc[i][j][e] = 0.f;                      \
    const uint32_t a_base = (uint32_t)((m0 + (lane & 15)) * GB_ROWB              \
                                       + (lane >> 4) * 16);                      \
    const uint32_t b_base = (uint32_t)((n0 + ((lane >> 4) & 1) * 8 + (lane & 7)) \
                                       * GB_ROWB + ((lane >> 3) & 1) * 16);      \
    GLOAD64(0, 0); GLOAD64(1, 64);                                               \
    int sidx = 0;                                                                \
    for (int kt = 0; kt < 32; kt++) {                                            \
        if (kt + 1 < 32) { CP_WAIT1(); } else { CP_WAIT0(); }                    \
        __syncthreads();                                                         \
        if (kt + 2 < 32) {                                                       \
            int sn = sidx + 2; if (sn >= GB_NST) sn -= GB_NST;                   \
            GLOAD64(sn, (size_t)(kt + 2) * 64);                                  \
        }                                                                        \
        const uint32_t sA = sbase + sidx * GB_STAGE;                             \
        const uint32_t sB = sA + GB_TILE;                                        \
        _Pragma("unroll")                                                        \
        for (int ks = 0; ks < 4; ks++) {                                         \
            const uint32_t kb = ks * 32;                                         \
            uint32_t af[4][4], bp[2][4];                                         \
            _Pragma("unroll")                                                    \
            for (int mt = 0; mt < 4; mt++)                                       \
                ldm_x4(af[mt], sA + a_base + mt * (16 * GB_ROWB) + kb);          \
            _Pragma("unroll")                                                    \
            for (int p = 0; p < 2; p++)                                          \
                ldm_x4(bp[p], sB + b_base + p * (16 * GB_ROWB) + kb);            \
            _Pragma("unroll")                                                    \
            for (int mt = 0; mt < 4; mt++)                                       \
                _Pragma("unroll")                                                \
                for (int nt = 0; nt < 4; nt++)                                   \
                    mma16816h(acc[mt][nt], af[mt], &bp[nt >> 1][(nt & 1) * 2]);  \
        }                                                                        \
        sidx++; if (sidx >= GB_NST) sidx -= GB_NST;                              \
    }

// ================= fused QKV GEMM: C = x @ Wqkv, epilogue does RoPE + fp16 =================
__global__ __launch_bounds__(256, 2)
void gemm_qkv(const __half* __restrict__ Ah, const __half* __restrict__ Bh,
              const int* __restrict__ positions,
              __half* __restrict__ qf, __half* __restrict__ kf, __half* __restrict__ vf)
{
    extern __shared__ char smc[];
    const uint32_t sbase = smem_to_u32(smc);
    const int tid  = threadIdx.x;
    const int lane = tid & 31;
    const int wid  = tid >> 5;
    const int bx = blockIdx.x;
    const int by = blockIdx.y;
    const int m0 = (wid & 1) * 64;
    const int n0 = (wid >> 1) * 32;

    GEMM_MAINLOOP64(Ah, Bh)

    const int g  = lane >> 2;
    const int tg = (lane & 3) * 2;
    const float scale = 0.08838834764831845f;
#pragma unroll
    for (int mt = 0; mt < 4; mt++) {
        const int r0 = by * 128 + m0 + mt * 16 + g;
        const int p0 = positions[r0];
        const int p1 = positions[r0 + 8];
#pragma unroll
        for (int nt = 0; nt < 4; nt++) {
            const int cc = bx * 128 + n0 + nt * 8 + tg;
            float v00 = acc[mt][nt][0], v01 = acc[mt][nt][1];
            float v10 = acc[mt][nt][2], v11 = acc[mt][nt][3];
            if (bx < 16) {
                const int pair = (cc & 127) >> 1;
                float2 c0 = g_rope[(p0 << 6) + pair];
                float2 c1 = g_rope[(p1 << 6) + pair];
                *(uint32_t*)(qf + (size_t)r0 * DIM + cc) =
                    packh((v00 * c0.x - v01 * c0.y) * scale,
                          (v00 * c0.y + v01 * c0.x) * scale);
                *(uint32_t*)(qf + (size_t)(r0 + 8) * DIM + cc) =
                    packh((v10 * c1.x - v11 * c1.y) * scale,
                          (v10 * c1.y + v11 * c1.x) * scale);
            } else if (bx < 24) {
                const int pair = (cc & 127) >> 1;
                float2 c0 = g_rope[(p0 << 6) + pair];
                float2 c1 = g_rope[(p1 << 6) + pair];
                const int c2 = cc - 2048;
                *(uint32_t*)(kf + (size_t)r0 * KV_DIM + c2) =
                    packh(v00 * c0.x - v01 * c0.y, v00 * c0.y + v01 * c0.x);
                *(uint32_t*)(kf + (size_t)(r0 + 8) * KV_DIM + c2) =
                    packh(v10 * c1.x - v11 * c1.y, v10 * c1.y + v11 * c1.x);
            } else {
                const int c2 = cc - 3072;
                *(uint32_t*)(vf + (size_t)r0 * KV_DIM + c2) = packh(v00, v01);
                *(uint32_t*)(vf + (size_t)(r0 + 8) * KV_DIM + c2) = packh(v10, v11);
            }
        }
    }
}

// ================= plain fp16 GEMM with fp32 output (wo) =================
__global__ __launch_bounds__(256, 2)
void gemm_h1(const __half* __restrict__ Ah, const __half* __restrict__ Bh,
             float* __restrict__ C, int Ncols)
{
    extern __shared__ char smc[];
    const uint32_t sbase = smem_to_u32(smc);
    const int tid  = threadIdx.x;
    const int lane = tid & 31;
    const int wid  = tid >> 5;
    const int bx = blockIdx.x;
    const int by = blockIdx.y;
    const int m0 = (wid & 1) * 64;
    const int n0 = (wid >> 1) * 32;

    GEMM_MAINLOOP64(Ah, Bh)

    const int g  = lane >> 2;
    const int tg = (lane & 3) * 2;
#pragma unroll
    for (int mt = 0; mt < 4; mt++) {
        const int r = by * 128 + m0 + mt * 16 + g;
#pragma unroll
        for (int nt = 0; nt < 4; nt++) {
            const int cc = bx * 128 + n0 + nt * 8 + tg;
            *(float2*)(C + (size_t)r * Ncols + cc) =
                make_float2(acc[mt][nt][0], acc[mt][nt][1]);
            *(float2*)(C + (size_t)(r + 8) * Ncols + cc) =
                make_float2(acc[mt][nt][2], acc[mt][nt][3]);
        }
    }
}

// ---------------- rope table: cos/sin per (pos, pair), computed in double ----------------
__global__ __launch_bounds__(256)
void rope_table()
{
    int idx = blockIdx.x * blockDim.x + threadIdx.x;
    if (idx >= S_LEN * 64) return;
    int pos = idx >> 6, pair = idx & 63;
    double inv = pow(10000.0, -(double)(2 * pair) / 128.0);
    double ang = (double)pos * inv;
    g_rope[idx] = make_float2((float)cos(ang), (float)sin(ang));
}

// ---------------- fp32 -> fp16 ----------------
__global__ __launch_bounds__(256)
void convert_h(const float* __restrict__ X, __half* __restrict__ H, int total)
{
    int i = blockIdx.x * blockDim.x + threadIdx.x;
    if (i >= total) return;
    H[i] = __float2half_rn(X[i]);
}

// ---------------- all 4 weight transposes in one launch ----------------
__global__ __launch_bounds__(256)
void transpose_all(const float* __restrict__ wq, const float* __restrict__ wk,
                   const float* __restrict__ wv, const float* __restrict__ wo,
                   __half* __restrict__ wqkvT, __half* __restrict__ woT)
{
    const int z = blockIdx.z;
    const float* W;
    __half* Th;
    int N;
    if (z == 0)      { W = wq; Th = wqkvT;              N = 2048; }
    else if (z == 1) { W = wk; Th = wqkvT + 2048 * DIM; N = 1024; }
    else if (z == 2) { W = wv; Th = wqkvT + 3072 * DIM; N = 1024; }
    else             { W = wo; Th = woT;                N = 2048; }

    int n0 = blockIdx.x * 32;
    if (n0 >= N) return;
    int k0 = blockIdx.y * 32;

    __shared__ float t[32][33];
    int tx = threadIdx.x & 31, ty = threadIdx.x >> 5;
#pragma unroll
    for (int j = 0; j < 4; j++)
        t[ty + j * 8][tx] = W[(size_t)(k0 + ty + j * 8) * N + n0 + tx];
    __syncthreads();
#pragma unroll
    for (int j = 0; j < 4; j++)
        Th[(size_t)(n0 + ty + j * 8) * DIM + k0 + tx] = __float2half_rn(t[tx][ty + j * 8]);
}

// ================= mma.sync flash attention (causal, GQA rep=2) =================
#define AQ_ROWB 272
#define AQ_TILE (128 * AQ_ROWB)        // 34816
#define AKV_TILE (64 * AQ_ROWB)        // 17408
#define AKV_BUF (2 * AKV_TILE)         // 34816 (K + V)
#define AT_SMEM (AQ_TILE + 2 * AKV_BUF)   // 104448 B

__global__ __launch_bounds__(256, 1)
void attn_mma(const __half* __restrict__ qf, const __half* __restrict__ kf,
              const __half* __restrict__ vf, __half* __restrict__ oh)
{
    extern __shared__ char smb[];
    const uint32_t sb  = smem_to_u32(smb);
    const uint32_t sQ  = sb;
    const uint32_t kv0 = sb + AQ_TILE;

    const int tid  = threadIdx.x;
    const int lane = tid & 31;
    const int wid  = tid >> 5;
    const int qt = blockIdx.x, h = blockIdx.y, b = blockIdx.z;
    const int kvh = h >> 1;
    const int q0 = qt * 128;
    const int m0 = wid * 16;
    const int g  = lane >> 2;
    const int tg = lane & 3;

    {
        const __half* srcQ = qf + (size_t)(b * S_LEN + q0) * DIM + h * HD;
        for (int c = tid; c < 2048; c += 256) {
            int r = c >> 4, cc = c & 15;
            CP_ASYNC16(sQ + r * AQ_ROWB + cc * 16, srcQ + (size_t)r * DIM + cc * 8);
        }
        CP_COMMIT();
    }

    const size_t kvbase0 = (size_t)(b * S_LEN) * KV_DIM + kvh * HD;

    {
        const __half* pK = kf + kvbase0;
        const __half* pV = vf + kvbase0;
        for (int c = tid; c < 1024; c += 256) {
            int r = c >> 4, cc = c & 15;
            uint32_t so = r * AQ_ROWB + cc * 16;
            size_t go = (size_t)r * KV_DIM + cc * 8;
            CP_ASYNC16(kv0 + 0 * AKV_TILE + so, pK + go);
            CP_ASYNC16(kv0 + 1 * AKV_TILE + so, pV + go);
        }
        CP_COMMIT();
    }

    float oacc[16][4];
#pragma unroll
    for (int nt = 0; nt < 16; nt++)
#pragma unroll
        for (int e = 0; e < 4; e++) oacc[nt][e] = 0.f;
    float mst0 = -1e30f, mst1 = -1e30f, lst0 = 0.f, lst1 = 0.f;

    const uint32_t qa_off = (uint32_t)((m0 + (lane & 15)) * AQ_ROWB + (lane >> 4) * 16);
    const uint32_t kb_row = (uint32_t)((lane & 7) * AQ_ROWB + ((lane >> 3) & 1) * 16);
    const uint32_t v_row  = (uint32_t)((lane & 15) * AQ_ROWB);

    const int ktmax = 2 * qt + 1;
    for (int kt = 0; kt <= ktmax; kt++) {
        const int cur = kt & 1;
        CP_WAIT0();
        __syncthreads();

        if (kt < ktmax) {
            const uint32_t kvn = kv0 + (cur ^ 1) * AKV_BUF;
            const size_t base = kvbase0 + (size_t)(kt + 1) * 64 * KV_DIM;
            const __half* pK = kf + base;
            const __half* pV = vf + base;
            for (int c = tid; c < 1024; c += 256) {
                int r = c >> 4, cc = c & 15;
                uint32_t so = r * AQ_ROWB + cc * 16;
                size_t go = (size_t)r * KV_DIM + cc * 8;
                CP_ASYNC16(kvn + 0 * AKV_TILE + so, pK + go);
                CP_ASYNC16(kvn + 1 * AKV_TILE + so, pV + go);
            }
            CP_COMMIT();
        }

        const uint32_t sK = kv0 + cur * AKV_BUF;
        const uint32_t sV = sK + AKV_TILE;

        float sacc[8][4];
#pragma unroll
        for (int j = 0; j < 8; j++)
#pragma unroll
            for (int e = 0; e < 4; e++) sacc[j][e] = 0.f;

#pragma unroll
        for (int kk = 0; kk < 8; kk++) {
            uint32_t qfr[4], kfr[2];
            ldm_x4(qfr, sQ + qa_off + kk * 32);
#pragma unroll
            for (int j = 0; j < 8; j++) {
                ldm_x2(kfr, sK + j * 8 * AQ_ROWB + kb_row + kk * 32);
                mma16816h(sacc[j], qfr, kfr);
            }
        }

        if (kt * 64 + 63 > q0 + m0 + g) {
            const int r0l = q0 + m0 + g, r1l = r0l + 8;
            const int cb = kt * 64 + tg * 2;
#pragma unroll
            for (int j = 0; j < 8; j++) {
                const int c0 = cb + j * 8;
                if (c0     > r0l) sacc[j][0] = -1e30f;
                if (c0 + 1 > r0l) sacc[j][1] = -1e30f;
                if (c0     > r1l) sacc[j][2] = -1e30f;
                if (c0 + 1 > r1l) sacc[j][3] = -1e30f;
            }
        }

        float mx0 = -1e30f, mx1 = -1e30f;
#pragma unroll
        for (int j = 0; j < 8; j++) {
            mx0 = fmaxf(mx0, fmaxf(sacc[j][0], sacc[j][1]));
            mx1 = fmaxf(mx1, fmaxf(sacc[j][2], sacc[j][3]));
        }
        mx0 = fmaxf(mx0, __shfl_xor_sync(0xffffffffu, mx0, 1));
        mx0 = fmaxf(mx0, __shfl_xor_sync(0xffffffffu, mx0, 2));
        mx1 = fmaxf(mx1, __shfl_xor_sync(0xffffffffu, mx1, 1));
        mx1 = fmaxf(mx1, __shfl_xor_sync(0xffffffffu, mx1, 2));
        const float nm0 = fmaxf(mst0, mx0);
        const float nm1 = fmaxf(mst1, mx1);
        const float a0 = expf(mst0 - nm0);
        const float a1 = expf(mst1 - nm1);
        mst0 = nm0; mst1 = nm1;
        float sum0 = 0.f, sum1 = 0.f;
#pragma unroll
        for (int j = 0; j < 8; j++) {
            sacc[j][0] = expf(sacc[j][0] - nm0);
            sacc[j][1] = expf(sacc[j][1] - nm0);
            sacc[j][2] = expf(sacc[j][2] - nm1);
            sacc[j][3] = expf(sacc[j][3] - nm1);
            sum0 += sacc[j][0] + sacc[j][1];
            sum1 += sacc[j][2] + sacc[j][3];
        }
        sum0 += __shfl_xor_sync(0xffffffffu, sum0, 1);
        sum0 += __shfl_xor_sync(0xffffffffu, sum0, 2);
        sum1 += __shfl_xor_sync(0xffffffffu, sum1, 1);
        sum1 += __shfl_xor_sync(0xffffffffu, sum1, 2);
        lst0 = lst0 * a0 + sum0;
        lst1 = lst1 * a1 + sum1;
#pragma unroll
        for (int nt = 0; nt < 16; nt++) {
            oacc[nt][0] *= a0; oacc[nt][1] *= a0;
            oacc[nt][2] *= a1; oacc[nt][3] *= a1;
        }

#pragma unroll
        for (int jk = 0; jk < 4; jk++) {
            uint32_t pf[4];
#pragma unroll
            for (int q = 0; q < 2; q++) {
                const int j = 2 * jk + q;
                pf[2 * q + 0] = packh(sacc[j][0], sacc[j][1]);
                pf[2 * q + 1] = packh(sacc[j][2], sacc[j][3]);
            }
            const uint32_t vbase = jk * 16 * AQ_ROWB + v_row;
#pragma unroll
            for (int nt = 0; nt < 16; nt++) {
                uint32_t vfr[2];
                ldm_x2_trans(vfr, sV + vbase + nt * 16);
                mma16816h(oacc[nt], pf, vfr);
            }
        }
    }

    const float inv0 = 1.f / lst0;
    const float inv1 = 1.f / lst1;
    const size_t r0g = (size_t)(b * S_LEN + q0 + m0 + g);
    const size_t r1g = r0g + 8;
    const int colb = h * HD + tg * 2;
#pragma unroll
    for (int nt = 0; nt < 16; nt++) {
        uint32_t hw0 = packh(oacc[nt][0] * inv0, oacc[nt][1] * inv0);
        uint32_t hw1 = packh(oacc[nt][2] * inv1, oacc[nt][3] * inv1);
        const int cc = colb + nt * 8;
        *(uint32_t*)(oh + r0g * DIM + cc) = hw0;
        *(uint32_t*)(oh + r1g * DIM + cc) = hw1;
    }
}

// ---------------- launcher ----------------
extern "C" void kernel_launch(void* const* d_in, const int* in_sizes, int n_in,
                              void* d_out, int out_size)
{
    const float* x  = (const float*)d_in[0];
    const float* wq = (const float*)d_in[1];
    const float* wk = (const float*)d_in[2];
    const float* wv = (const float*)d_in[3];
    const float* wo = (const float*)d_in[4];
    const int* positions = (const int*)d_in[7];
    float* out = (float*)d_out;

    __half *xf, *af, *wqkvT, *woT, *pqf, *pkf, *pvf;
    cudaGetSymbolAddress((void**)&xf, g_xf);
    cudaGetSymbolAddress((void**)&af, g_af);
    cudaGetSymbolAddress((void**)&wqkvT, g_wqkvT);
    cudaGetSymbolAddress((void**)&woT, g_woT);
    cudaGetSymbolAddress((void**)&pqf, g_qf);
    cudaGetSymbolAddress((void**)&pkf, g_kf);
    cudaGetSymbolAddress((void**)&pvf, g_vf);

    cudaFuncSetAttribute(gemm_qkv, cudaFuncAttributeMaxDynamicSharedMemorySize, GB_TOTAL);
    cudaFuncSetAttribute(gemm_h1,  cudaFuncAttributeMaxDynamicSharedMemorySize, GB_TOTAL);
    cudaFuncSetAttribute(attn_mma, cudaFuncAttributeMaxDynamicSharedMemorySize, AT_SMEM);

    // 1: rope table
    rope_table<<<(S_LEN * 64 + 255) / 256, 256>>>();
    // 2: x -> fp16
    {
        int total = T_TOK * DIM;
        convert_h<<<(total + 255) / 256, 256>>>(x, xf, total);
    }
    // 3: all weight transposes in one launch
    transpose_all<<<dim3(64, 64, 4), 256>>>(wq, wk, wv, wo, wqkvT, woT);
    // 4: fused QKV GEMM + RoPE + fp16 epilogue
    gemm_qkv<<<dim3(QKV_N / 128, T_TOK / 128), 256, GB_TOTAL>>>(xf, wqkvT, positions,
                                                                pqf, pkf, pvf);
    // 5: flash attention
    attn_mma<<<dim3(S_LEN / 128, NH, B_SZ), 256, AT_SMEM>>>(pqf, pkf, pvf, af);
    // 6: output projection
    gemm_h1<<<dim3(DIM / 128, T_TOK / 128), 256, GB_TOTAL>>>(af, woT, out, DIM);
}

// round 17
// speedup vs baseline: 5.5674x; 1.0094x over previous
#include <cuda_runtime.h>
#include <cuda_bf16.h>
#include <cuda_fp16.h>
#include <cstdint>
#include <math.h>

// ---------------- problem constants ----------------
#define T_TOK   8192
#define DIM     2048
#define NH      16
#define NKV     8
#define HD      128
#define S_LEN   1024
#define B_SZ    8
#define KV_DIM  1024      // NKV * HD
#define QKV_N   4096      // DIM + 2*KV_DIM

// ---------------- scratch ----------------
__device__ float2 g_rope[S_LEN * 64];      // cos/sin per (pos, pair)

// fp16 activations
__device__ __half g_xf[T_TOK * DIM];       // x single fp16 (QKV gemm A)
__device__ __half g_af[T_TOK * DIM];       // attn out single fp16 (wo gemm A)
// fp16 transposed weights [N,K]
__device__ __half g_wqkvT[QKV_N * DIM];    // rows: 0-2047 wq^T, 2048-3071 wk^T, 3072-4095 wv^T
__device__ __half g_woT[DIM * DIM];
// fp16 attention operands (written by fused QKV gemm epilogue)
__device__ __half g_qf[T_TOK * DIM];       // q (roped, scaled) fp16
__device__ __half g_kf[T_TOK * KV_DIM];    // k (roped) fp16
__device__ __half g_vf[T_TOK * KV_DIM];    // v fp16

// ================= low-level helpers (sm_80-class PTX only) =================
__device__ __forceinline__ uint32_t smem_to_u32(const void* smem_ptr) {
    uint32_t addr;
    asm("{ .reg .u64 tmp; cvta.to.shared.u64 tmp, %1; cvt.u32.u64 %0, tmp; }"
        : "=r"(addr) : "l"(smem_ptr));
    return addr;
}

#define CP_ASYNC16(dst_u32, src_ptr) \
    asm volatile("cp.async.cg.shared.global [%0], [%1], 16;" \
                 :: "r"(dst_u32), "l"(src_ptr) : "memory")
#define CP_COMMIT() asm volatile("cp.async.commit_group;" ::: "memory")
#define CP_WAIT0()  asm volatile("cp.async.wait_group 0;" ::: "memory")
#define CP_WAIT1()  asm volatile("cp.async.wait_group 1;" ::: "memory")

__device__ __forceinline__ void ldm_x4(uint32_t* r, uint32_t addr) {
    asm volatile("ldmatrix.sync.aligned.m8n8.x4.shared.b16 {%0,%1,%2,%3}, [%4];"
                 : "=r"(r[0]), "=r"(r[1]), "=r"(r[2]), "=r"(r[3]) : "r"(addr));
}
__device__ __forceinline__ void ldm_x2_trans(uint32_t* r, uint32_t addr) {
    asm volatile("ldmatrix.sync.aligned.m8n8.x2.trans.shared.b16 {%0,%1}, [%2];"
                 : "=r"(r[0]), "=r"(r[1]) : "r"(addr));
}
__device__ __forceinline__ void ldm_x2(uint32_t* r, uint32_t addr) {
    asm volatile("ldmatrix.sync.aligned.m8n8.x2.shared.b16 {%0,%1}, [%2];"
                 : "=r"(r[0]), "=r"(r[1]) : "r"(addr));
}
// fp16 mma
__device__ __forceinline__ void mma16816h(float* c, const uint32_t* a, const uint32_t* b) {
    asm volatile("mma.sync.aligned.m16n8k16.row.col.f32.f16.f16.f32 "
                 "{%0,%1,%2,%3}, {%4,%5,%6,%7}, {%8,%9}, {%0,%1,%2,%3};"
                 : "+f"(c[0]), "+f"(c[1]), "+f"(c[2]), "+f"(c[3])
                 : "r"(a[0]), "r"(a[1]), "r"(a[2]), "r"(a[3]), "r"(b[0]), "r"(b[1]));
}
__device__ __forceinline__ uint32_t packh(float lo, float hi) {
    __half2 h = __floats2half2_rn(lo, hi);
    return *(uint32_t*)&h;
}

// ================= GEMM tiling: CTA 128x128, K-tile 64, 3-stage =================
#define GB_ROWB   144
#define GB_TILE   (128 * GB_ROWB)          // 18432 B
#define GB_STAGE  (2 * GB_TILE)            // A + B = 36864 B
#define GB_NST    3
#define GB_TOTAL  (GB_NST * GB_STAGE)      // 110592 B -> 2 CTAs/SM

// 8 cp.async per thread per stage (4 A row-chunks + 4 B), K fixed at 2048.
#define GLOAD64(sidx, ko)                                                        \
    do {                                                                         \
        const uint32_t st_ = sbase + (sidx) * GB_STAGE;                          \
        CP_ASYNC16(st_ + so0 +  0 * 4608, Ah + ga0 +  0 * 65536 + (ko));         \
        CP_ASYNC16(st_ + so0 +  1 * 4608, Ah + ga0 +  1 * 65536 + (ko));         \
        CP_ASYNC16(st_ + so0 +  2 * 4608, Ah + ga0 +  2 * 65536 + (ko));         \
        CP_ASYNC16(st_ + so0 +  3 * 4608, Ah + ga0 +  3 * 65536 + (ko));         \
        CP_ASYNC16(st_ + GB_TILE + so0 + 0 * 4608, Bh + gb0 + 0 * 65536 + (ko)); \
        CP_ASYNC16(st_ + GB_TILE + so0 + 1 * 4608, Bh + gb0 + 1 * 65536 + (ko)); \
        CP_ASYNC16(st_ + GB_TILE + so0 + 2 * 4608, Bh + gb0 + 2 * 65536 + (ko)); \
        CP_ASYNC16(st_ + GB_TILE + so0 + 3 * 4608, Bh + gb0 + 3 * 65536 + (ko)); \
        CP_COMMIT();                                                             \
    } while (0)

// mainloop: K = 2048 fixed, 32 K-tiles of 64; single barrier per tile.
// Inner schedule: per ks load B pair + A(mt0), then roll: ldm A(mt+1) before mt's MMAs.
#define GEMM_MAINLOOP64(Ah, Bh)                                                  \
    const int c8  = tid & 7;                                                     \
    const int r0c = tid >> 3;                                                    \
    const size_t ga0 = (size_t)(by * 128 + r0c) * 2048 + c8 * 8;                 \
    const size_t gb0 = (size_t)(bx * 128 + r0c) * 2048 + c8 * 8;                 \
    const uint32_t so0 = r0c * GB_ROWB + c8 * 16;                                \
    float acc[4][4][4];                                                          \
    _Pragma("unroll")                                                            \
    for (int i = 0; i < 4; i++)                                                  \
        _Pragma("unroll")                                                        \
        for (int j = 0; j < 4; j++)                                              \
            _Pragma("unroll")                                                    \
            for (int e = 0; e < 4; e++) acc[i][j][e] = 0.f;                      \
    const uint32_t a_base = (uint32_t)((m0 + (lane & 15)) * GB_ROWB              \
                                       + (lane >> 4) * 16);                      \
    const uint32_t b_base = (uint32_t)((n0 + ((lane >> 4) & 1) * 8 + (lane & 7)) \
                                       * GB_ROWB + ((lane >> 3) & 1) * 16);      \
    GLOAD64(0, 0); GLOAD64(1, 64);                                               \
    int sidx = 0;                                                                \
    for (int kt = 0; kt < 32; kt++) {                                            \
        if (kt + 1 < 32) { CP_WAIT1(); } else { CP_WAIT0(); }                    \
        __syncthreads();                                                         \
        if (kt + 2 < 32) {                                                       \
            int sn = sidx + 2; if (sn >= GB_NST) sn -= GB_NST;                   \
            GLOAD64(sn, (size_t)(kt + 2) * 64);                                  \
        }                                                                        \
        const uint32_t sA = sbase + sidx * GB_STAGE;                             \
        const uint32_t sB = sA + GB_TILE;                                        \
        _Pragma("unroll")                                                        \
        for (int ks = 0; ks < 4; ks++) {                                         \
            const uint32_t kb = ks * 32;                                         \
            uint32_t bp[2][4], af[2][4];                                         \
            ldm_x4(bp[0], sB + b_base + 0 * (16 * GB_ROWB) + kb);                \
            ldm_x4(bp[1], sB + b_base + 1 * (16 * GB_ROWB) + kb);                \
            ldm_x4(af[0], sA + a_base + 0 * (16 * GB_ROWB) + kb);                \
            _Pragma("unroll")                                                    \
            for (int mt = 0; mt < 4; mt++) {                                     \
                if (mt < 3)                                                      \
                    ldm_x4(af[(mt + 1) & 1],                                     \
                           sA + a_base + (mt + 1) * (16 * GB_ROWB) + kb);        \
                _Pragma("unroll")                                                \
                for (int nt = 0; nt < 4; nt++)                                   \
                    mma16816h(acc[mt][nt], af[mt & 1],                           \
                              &bp[nt >> 1][(nt & 1) * 2]);                       \
            }                                                                    \
        }                                                                        \
        sidx++; if (sidx >= GB_NST) sidx -= GB_NST;                              \
    }

// ================= fused QKV GEMM: C = x @ Wqkv, epilogue does RoPE + fp16 =================
__global__ __launch_bounds__(256, 2)
void gemm_qkv(const __half* __restrict__ Ah, const __half* __restrict__ Bh,
              const int* __restrict__ positions,
              __half* __restrict__ qf, __half* __restrict__ kf, __half* __restrict__ vf)
{
    extern __shared__ char smc[];
    const uint32_t sbase = smem_to_u32(smc);
    const int tid  = threadIdx.x;
    const int lane = tid & 31;
    const int wid  = tid >> 5;
    const int bx = blockIdx.x;
    const int by = blockIdx.y;
    const int m0 = (wid & 1) * 64;
    const int n0 = (wid >> 1) * 32;

    GEMM_MAINLOOP64(Ah, Bh)

    const int g  = lane >> 2;
    const int tg = (lane & 3) * 2;
    const float scale = 0.08838834764831845f;
#pragma unroll
    for (int mt = 0; mt < 4; mt++) {
        const int r0 = by * 128 + m0 + mt * 16 + g;
        const int p0 = positions[r0];
        const int p1 = positions[r0 + 8];
#pragma unroll
        for (int nt = 0; nt < 4; nt++) {
            const int cc = bx * 128 + n0 + nt * 8 + tg;
            float v00 = acc[mt][nt][0], v01 = acc[mt][nt][1];
            float v10 = acc[mt][nt][2], v11 = acc[mt][nt][3];
            if (bx < 16) {
                const int pair = (cc & 127) >> 1;
                float2 c0 = g_rope[(p0 << 6) + pair];
                float2 c1 = g_rope[(p1 << 6) + pair];
                *(uint32_t*)(qf + (size_t)r0 * DIM + cc) =
                    packh((v00 * c0.x - v01 * c0.y) * scale,
                          (v00 * c0.y + v01 * c0.x) * scale);
                *(uint32_t*)(qf + (size_t)(r0 + 8) * DIM + cc) =
                    packh((v10 * c1.x - v11 * c1.y) * scale,
                          (v10 * c1.y + v11 * c1.x) * scale);
            } else if (bx < 24) {
                const int pair = (cc & 127) >> 1;
                float2 c0 = g_rope[(p0 << 6) + pair];
                float2 c1 = g_rope[(p1 << 6) + pair];
                const int c2 = cc - 2048;
                *(uint32_t*)(kf + (size_t)r0 * KV_DIM + c2) =
                    packh(v00 * c0.x - v01 * c0.y, v00 * c0.y + v01 * c0.x);
                *(uint32_t*)(kf + (size_t)(r0 + 8) * KV_DIM + c2) =
                    packh(v10 * c1.x - v11 * c1.y, v10 * c1.y + v11 * c1.x);
            } else {
                const int c2 = cc - 3072;
                *(uint32_t*)(vf + (size_t)r0 * KV_DIM + c2) = packh(v00, v01);
                *(uint32_t*)(vf + (size_t)(r0 + 8) * KV_DIM + c2) = packh(v10, v11);
            }
        }
    }
}

// ================= plain fp16 GEMM with fp32 output (wo) =================
__global__ __launch_bounds__(256, 2)
void gemm_h1(const __half* __restrict__ Ah, const __half* __restrict__ Bh,
             float* __restrict__ C, int Ncols)
{
    extern __shared__ char smc[];
    const uint32_t sbase = smem_to_u32(smc);
    const int tid  = threadIdx.x;
    const int lane = tid & 31;
    const int wid  = tid >> 5;
    const int bx = blockIdx.x;
    const int by = blockIdx.y;
    const int m0 = (wid & 1) * 64;
    const int n0 = (wid >> 1) * 32;

    GEMM_MAINLOOP64(Ah, Bh)

    const int g  = lane >> 2;
    const int tg = (lane & 3) * 2;
#pragma unroll
    for (int mt = 0; mt < 4; mt++) {
        const int r = by * 128 + m0 + mt * 16 + g;
#pragma unroll
        for (int nt = 0; nt < 4; nt++) {
            const int cc = bx * 128 + n0 + nt * 8 + tg;
            *(float2*)(C + (size_t)r * Ncols + cc) =
                make_float2(acc[mt][nt][0], acc[mt][nt][1]);
            *(float2*)(C + (size_t)(r + 8) * Ncols + cc) =
                make_float2(acc[mt][nt][2], acc[mt][nt][3]);
        }
    }
}

// ---------------- rope table: cos/sin per (pos, pair), computed in double ----------------
__global__ __launch_bounds__(256)
void rope_table()
{
    int idx = blockIdx.x * blockDim.x + threadIdx.x;
    if (idx >= S_LEN * 64) return;
    int pos = idx >> 6, pair = idx & 63;
    double inv = pow(10000.0, -(double)(2 * pair) / 128.0);
    double ang = (double)pos * inv;
    g_rope[idx] = make_float2((float)cos(ang), (float)sin(ang));
}

// ---------------- fp32 -> fp16 ----------------
__global__ __launch_bounds__(256)
void convert_h(const float* __restrict__ X, __half* __restrict__ H, int total)
{
    int i = blockIdx.x * blockDim.x + threadIdx.x;
    if (i >= total) return;
    H[i] = __float2half_rn(X[i]);
}

// ---------------- all 4 weight transposes in one launch ----------------
__global__ __launch_bounds__(256)
void transpose_all(const float* __restrict__ wq, const float* __restrict__ wk,
                   const float* __restrict__ wv, const float* __restrict__ wo,
                   __half* __restrict__ wqkvT, __half* __restrict__ woT)
{
    const int z = blockIdx.z;
    const float* W;
    __half* Th;
    int N;
    if (z == 0)      { W = wq; Th = wqkvT;              N = 2048; }
    else if (z == 1) { W = wk; Th = wqkvT + 2048 * DIM; N = 1024; }
    else if (z == 2) { W = wv; Th = wqkvT + 3072 * DIM; N = 1024; }
    else             { W = wo; Th = woT;                N = 2048; }

    int n0 = blockIdx.x * 32;
    if (n0 >= N) return;
    int k0 = blockIdx.y * 32;

    __shared__ float t[32][33];
    int tx = threadIdx.x & 31, ty = threadIdx.x >> 5;
#pragma unroll
    for (int j = 0; j < 4; j++)
        t[ty + j * 8][tx] = W[(size_t)(k0 + ty + j * 8) * N + n0 + tx];
    __syncthreads();
#pragma unroll
    for (int j = 0; j < 4; j++)
        Th[(size_t)(n0 + ty + j * 8) * DIM + k0 + tx] = __float2half_rn(t[tx][ty + j * 8]);
}

// ================= mma.sync flash attention (causal, GQA rep=2) =================
#define AQ_ROWB 272
#define AQ_TILE (128 * AQ_ROWB)        // 34816
#define AKV_TILE (64 * AQ_ROWB)        // 17408
#define AKV_BUF (2 * AKV_TILE)         // 34816 (K + V)
#define AT_SMEM (AQ_TILE + 2 * AKV_BUF)   // 104448 B

__global__ __launch_bounds__(256, 1)
void attn_mma(const __half* __restrict__ qf, const __half* __restrict__ kf,
              const __half* __restrict__ vf, __half* __restrict__ oh)
{
    extern __shared__ char smb[];
    const uint32_t sb  = smem_to_u32(smb);
    const uint32_t sQ  = sb;
    const uint32_t kv0 = sb + AQ_TILE;

    const int tid  = threadIdx.x;
    const int lane = tid & 31;
    const int wid  = tid >> 5;
    const int qt = blockIdx.x, h = blockIdx.y, b = blockIdx.z;
    const int kvh = h >> 1;
    const int q0 = qt * 128;
    const int m0 = wid * 16;
    const int g  = lane >> 2;
    const int tg = lane & 3;

    {
        const __half* srcQ = qf + (size_t)(b * S_LEN + q0) * DIM + h * HD;
        for (int c = tid; c < 2048; c += 256) {
            int r = c >> 4, cc = c & 15;
            CP_ASYNC16(sQ + r * AQ_ROWB + cc * 16, srcQ + (size_t)r * DIM + cc * 8);
        }
        CP_COMMIT();
    }

    const size_t kvbase0 = (size_t)(b * S_LEN) * KV_DIM + kvh * HD;

    {
        const __half* pK = kf + kvbase0;
        const __half* pV = vf + kvbase0;
        for (int c = tid; c < 1024; c += 256) {
            int r = c >> 4, cc = c & 15;
            uint32_t so = r * AQ_ROWB + cc * 16;
            size_t go = (size_t)r * KV_DIM + cc * 8;
            CP_ASYNC16(kv0 + 0 * AKV_TILE + so, pK + go);
            CP_ASYNC16(kv0 + 1 * AKV_TILE + so, pV + go);
        }
        CP_COMMIT();
    }

    float oacc[16][4];
#pragma unroll
    for (int nt = 0; nt < 16; nt++)
#pragma unroll
        for (int e = 0; e < 4; e++) oacc[nt][e] = 0.f;
    float mst0 = -1e30f, mst1 = -1e30f, lst0 = 0.f, lst1 = 0.f;

    const uint32_t qa_off = (uint32_t)((m0 + (lane & 15)) * AQ_ROWB + (lane >> 4) * 16);
    const uint32_t kb_row = (uint32_t)((lane & 7) * AQ_ROWB + ((lane >> 3) & 1) * 16);
    const uint32_t v_row  = (uint32_t)((lane & 15) * AQ_ROWB);

    const int ktmax = 2 * qt + 1;
    for (int kt = 0; kt <= ktmax; kt++) {
        const int cur = kt & 1;
        CP_WAIT0();
        __syncthreads();

        if (kt < ktmax) {
            const uint32_t kvn = kv0 + (cur ^ 1) * AKV_BUF;
            const size_t base = kvbase0 + (size_t)(kt + 1) * 64 * KV_DIM;
            const __half* pK = kf + base;
            const __half* pV = vf + base;
            for (int c = tid; c < 1024; c += 256) {
                int r = c >> 4, cc = c & 15;
                uint32_t so = r * AQ_ROWB + cc * 16;
                size_t go = (size_t)r * KV_DIM + cc * 8;
                CP_ASYNC16(kvn + 0 * AKV_TILE + so, pK + go);
                CP_ASYNC16(kvn + 1 * AKV_TILE + so, pV + go);
            }
            CP_COMMIT();
        }

        const uint32_t sK = kv0 + cur * AKV_BUF;
        const uint32_t sV = sK + AKV_TILE;

        float sacc[8][4];
#pragma unroll
        for (int j = 0; j < 8; j++)
#pragma unroll
            for (int e = 0; e < 4; e++) sacc[j][e] = 0.f;

#pragma unroll
        for (int kk = 0; kk < 8; kk++) {
            uint32_t qfr[4], kfr[2];
            ldm_x4(qfr, sQ + qa_off + kk * 32);
#pragma unroll
            for (int j = 0; j < 8; j++) {
                ldm_x2(kfr, sK + j * 8 * AQ_ROWB + kb_row + kk * 32);
                mma16816h(sacc[j], qfr, kfr);
            }
        }

        if (kt * 64 + 63 > q0 + m0 + g) {
            const int r0l = q0 + m0 + g, r1l = r0l + 8;
            const int cb = kt * 64 + tg * 2;
#pragma unroll
            for (int j = 0; j < 8; j++) {
                const int c0 = cb + j * 8;
                if (c0     > r0l) sacc[j][0] = -1e30f;
                if (c0 + 1 > r0l) sacc[j][1] = -1e30f;
                if (c0     > r1l) sacc[j][2] = -1e30f;
                if (c0 + 1 > r1l) sacc[j][3] = -1e30f;
            }
        }

        float mx0 = -1e30f, mx1 = -1e30f;
#pragma unroll
        for (int j = 0; j < 8; j++) {
            mx0 = fmaxf(mx0, fmaxf(sacc[j][0], sacc[j][1]));
            mx1 = fmaxf(mx1, fmaxf(sacc[j][2], sacc[j][3]));
        }
        mx0 = fmaxf(mx0, __shfl_xor_sync(0xffffffffu, mx0, 1));
        mx0 = fmaxf(mx0, __shfl_xor_sync(0xffffffffu, mx0, 2));
        mx1 = fmaxf(mx1, __shfl_xor_sync(0xffffffffu, mx1, 1));
        mx1 = fmaxf(mx1, __shfl_xor_sync(0xffffffffu, mx1, 2));
        const float nm0 = fmaxf(mst0, mx0);
        const float nm1 = fmaxf(mst1, mx1);
        const float a0 = expf(mst0 - nm0);
        const float a1 = expf(mst1 - nm1);
        mst0 = nm0; mst1 = nm1;
        float sum0 = 0.f, sum1 = 0.f;
#pragma unroll
        for (int j = 0; j < 8; j++) {
            sacc[j][0] = expf(sacc[j][0] - nm0);
            sacc[j][1] = expf(sacc[j][1] - nm0);
            sacc[j][2] = expf(sacc[j][2] - nm1);
            sacc[j][3] = expf(sacc[j][3] - nm1);
            sum0 += sacc[j][0] + sacc[j][1];
            sum1 += sacc[j][2] + sacc[j][3];
        }
        sum0 += __shfl_xor_sync(0xffffffffu, sum0, 1);
        sum0 += __shfl_xor_sync(0xffffffffu, sum0, 2);
        sum1 += __shfl_xor_sync(0xffffffffu, sum1, 1);
        sum1 += __shfl_xor_sync(0xffffffffu, sum1, 2);
        lst0 = lst0 * a0 + sum0;
        lst1 = lst1 * a1 + sum1;
#pragma unroll
        for (int nt = 0; nt < 16; nt++) {
            oacc[nt][0] *= a0; oacc[nt][1] *= a0;
            oacc[nt][2] *= a1; oacc[nt][3] *= a1;
        }

#pragma unroll
        for (int jk = 0; jk < 4; jk++) {
            uint32_t pf[4];
#pragma unroll
            for (int q = 0; q < 2; q++) {
                const int j = 2 * jk + q;
                pf[2 * q + 0] = packh(sacc[j][0], sacc[j][1]);
                pf[2 * q + 1] = packh(sacc[j][2], sacc[j][3]);
            }
            const uint32_t vbase = jk * 16 * AQ_ROWB + v_row;
#pragma unroll
            for (int nt = 0; nt < 16; nt++) {
                uint32_t vfr[2];
                ldm_x2_trans(vfr, sV + vbase + nt * 16);
                mma16816h(oacc[nt], pf, vfr);
            }
        }
    }

    const float inv0 = 1.f / lst0;
    const float inv1 = 1.f / lst1;
    const size_t r0g = (size_t)(b * S_LEN + q0 + m0 + g);
    const size_t r1g = r0g + 8;
    const int colb = h * HD + tg * 2;
#pragma unroll
    for (int nt = 0; nt < 16; nt++) {
        uint32_t hw0 = packh(oacc[nt][0] * inv0, oacc[nt][1] * inv0);
        uint32_t hw1 = packh(oacc[nt][2] * inv1, oacc[nt][3] * inv1);
        const int cc = colb + nt * 8;
        *(uint32_t*)(oh + r0g * DIM + cc) = hw0;
        *(uint32_t*)(oh + r1g * DIM + cc) = hw1;
    }
}

// ---------------- launcher ----------------
extern "C" void kernel_launch(void* const* d_in, const int* in_sizes, int n_in,
                              void* d_out, int out_size)
{
    const float* x  = (const float*)d_in[0];
    const float* wq = (const float*)d_in[1];
    const float* wk = (const float*)d_in[2];
    const float* wv = (const float*)d_in[3];
    const float* wo = (const float*)d_in[4];
    const int* positions = (const int*)d_in[7];
    float* out = (float*)d_out;

    __half *xf, *af, *wqkvT, *woT, *pqf, *pkf, *pvf;
    cudaGetSymbolAddress((void**)&xf, g_xf);
    cudaGetSymbolAddress((void**)&af, g_af);
    cudaGetSymbolAddress((void**)&wqkvT, g_wqkvT);
    cudaGetSymbolAddress((void**)&woT, g_woT);
    cudaGetSymbolAddress((void**)&pqf, g_qf);
    cudaGetSymbolAddress((void**)&pkf, g_kf);
    cudaGetSymbolAddress((void**)&pvf, g_vf);

    cudaFuncSetAttribute(gemm_qkv, cudaFuncAttributeMaxDynamicSharedMemorySize, GB_TOTAL);
    cudaFuncSetAttribute(gemm_h1,  cudaFuncAttributeMaxDynamicSharedMemorySize, GB_TOTAL);
    cudaFuncSetAttribute(attn_mma, cudaFuncAttributeMaxDynamicSharedMemorySize, AT_SMEM);

    // 1: rope table
    rope_table<<<(S_LEN * 64 + 255) / 256, 256>>>();
    // 2: x -> fp16
    {
        int total = T_TOK * DIM;
        convert_h<<<(total + 255) / 256, 256>>>(x, xf, total);
    }
    // 3: all weight transposes in one launch
    transpose_all<<<dim3(64, 64, 4), 256>>>(wq, wk, wv, wo, wqkvT, woT);
    // 4: fused QKV GEMM + RoPE + fp16 epilogue
    gemm_qkv<<<dim3(QKV_N / 128, T_TOK / 128), 256, GB_TOTAL>>>(xf, wqkvT, positions,
                                                                pqf, pkf, pvf);
    // 5: flash attention
    attn_mma<<<dim3(S_LEN / 128, NH, B_SZ), 256, AT_SMEM>>>(pqf, pkf, pvf, af);
    // 6: output projection
    gemm_h1<<<dim3(DIM / 128, T_TOK / 128), 256, GB_TOTAL>>>(af, woT, out, DIM);
}